// round 1
// baseline (speedup 1.0000x reference)
#include <cuda_runtime.h>

#define BATCH 8
#define SEQT 2048
#define CDIM 1024
#define HDIM 128
#define BT (BATCH * SEQT)   // 16384 rows

// Scratch for Q, K, V projections (8 MB each)
__device__ float g_Q[BT * HDIM];
__device__ float g_K[BT * HDIM];
__device__ float g_V[BT * HDIM];

// ---------------------------------------------------------------------------
// Projection GEMM: out[m,h] = sum_c x[m,c] * W[c,h] + b[h]
// M=16384, K=1024, N=128. grid.z selects (Wq,bq,gQ)/(Wk,bk,gK)/(Wv,bv,gV).
// Tile: 64 x 128 x 16, 256 threads, 4x8 register micro-tile per thread.
// ---------------------------------------------------------------------------
#define PBM 64
#define PBN 128
#define PBK 16

__global__ __launch_bounds__(256) void proj_kernel(
    const float* __restrict__ x,
    const float* __restrict__ Wq, const float* __restrict__ bq,
    const float* __restrict__ Wk, const float* __restrict__ bk,
    const float* __restrict__ Wv, const float* __restrict__ bv)
{
    const float* W;
    const float* bias;
    float* out;
    if (blockIdx.z == 0)      { W = Wq; bias = bq; out = g_Q; }
    else if (blockIdx.z == 1) { W = Wk; bias = bk; out = g_K; }
    else                      { W = Wv; bias = bv; out = g_V; }

    __shared__ float As[PBM][PBK + 1];   // x tile, padded (kill 2-way conflicts)
    __shared__ float Bs[PBK][PBN];       // W tile

    const int tid  = threadIdx.x;
    const int trow = tid >> 4;   // 0..15
    const int tcol = tid & 15;   // 0..15
    const int m0   = blockIdx.x * PBM;

    float acc[4][8];
#pragma unroll
    for (int i = 0; i < 4; i++)
#pragma unroll
        for (int j = 0; j < 8; j++) acc[i][j] = 0.0f;

    const int a_row = tid >> 2;         // 0..63
    const int a_c4  = (tid & 3) * 4;    // 0,4,8,12

    for (int k0 = 0; k0 < CDIM; k0 += PBK) {
        // Load As: 64x16 floats (one float4 per thread)
        float4 av = *reinterpret_cast<const float4*>(
            &x[(size_t)(m0 + a_row) * CDIM + k0 + a_c4]);
        As[a_row][a_c4 + 0] = av.x;
        As[a_row][a_c4 + 1] = av.y;
        As[a_row][a_c4 + 2] = av.z;
        As[a_row][a_c4 + 3] = av.w;

        // Load Bs: 16x128 floats (two float4 per thread)
#pragma unroll
        for (int s = 0; s < 2; s++) {
            int idx = tid + s * 256;          // 0..511
            int kr  = idx >> 5;               // 0..15
            int h4  = (idx & 31) * 4;         // 0..124
            *reinterpret_cast<float4*>(&Bs[kr][h4]) =
                *reinterpret_cast<const float4*>(&W[(size_t)(k0 + kr) * PBN + h4]);
        }
        __syncthreads();

#pragma unroll
        for (int k = 0; k < PBK; k++) {
            float a[4];
#pragma unroll
            for (int i = 0; i < 4; i++) a[i] = As[trow * 4 + i][k];
            float4 b0 = *reinterpret_cast<const float4*>(&Bs[k][tcol * 8]);
            float4 b1 = *reinterpret_cast<const float4*>(&Bs[k][tcol * 8 + 4]);
            float bb[8] = {b0.x, b0.y, b0.z, b0.w, b1.x, b1.y, b1.z, b1.w};
#pragma unroll
            for (int i = 0; i < 4; i++)
#pragma unroll
                for (int j = 0; j < 8; j++)
                    acc[i][j] += a[i] * bb[j];
        }
        __syncthreads();
    }

    // Store with bias
    float bb[8];
#pragma unroll
    for (int j = 0; j < 8; j++) bb[j] = bias[tcol * 8 + j];
#pragma unroll
    for (int i = 0; i < 4; i++) {
        int row = m0 + trow * 4 + i;
        float4 r0, r1;
        r0.x = acc[i][0] + bb[0]; r0.y = acc[i][1] + bb[1];
        r0.z = acc[i][2] + bb[2]; r0.w = acc[i][3] + bb[3];
        r1.x = acc[i][4] + bb[4]; r1.y = acc[i][5] + bb[5];
        r1.z = acc[i][6] + bb[6]; r1.w = acc[i][7] + bb[7];
        *reinterpret_cast<float4*>(&out[(size_t)row * HDIM + tcol * 8])     = r0;
        *reinterpret_cast<float4*>(&out[(size_t)row * HDIM + tcol * 8 + 4]) = r1;
    }
}

// ---------------------------------------------------------------------------
// Flash attention (fp32, causal). BQ=BK=64 tiles, 256 threads.
// Thread (trow,tcol) owns score micro-tile [4 rows x 4 cols] and output
// micro-tile [4 rows x 8 dims]. Row reductions via half-warp shuffles
// (each 16-thread row-group is a contiguous half-warp).
// ---------------------------------------------------------------------------
#define BQ 64
#define BKT 64
#define QS 132          // padded row stride for Q/K/V tiles (floats)
#define SS 68           // padded row stride for P tile (floats)
#define ATTN_SMEM ((BQ * QS * 3 + BQ * SS) * 4)   // 118784 bytes

__global__ __launch_bounds__(256) void attn_kernel(float* __restrict__ out)
{
    extern __shared__ float sm[];
    float* Qs = sm;                    // 64*132
    float* Ks = Qs + BQ * QS;          // 64*132
    float* Vs = Ks + BKT * QS;         // 64*132
    float* Ps = Vs + BKT * QS;         // 64*68

    const int tid   = threadIdx.x;
    const int trow  = tid >> 4;        // 0..15
    const int tcol  = tid & 15;        // 0..15
    const int qtile = gridDim.x - 1 - blockIdx.x;  // heavy tiles scheduled first
    const int b     = blockIdx.y;
    const int q0    = qtile * BQ;
    const float scale = 0.03125f;      // 1024^-0.5

    // Load Q tile [64 x 128] into padded smem
    const float* Qg = g_Q + (size_t)(b * SEQT + q0) * HDIM;
#pragma unroll
    for (int s = 0; s < 8; s++) {
        int idx = tid + s * 256;       // 0..2047 float4 slots
        int r   = idx >> 5;            // 0..63
        int d4  = (idx & 31) * 4;      // 0..124
        *reinterpret_cast<float4*>(&Qs[r * QS + d4]) =
            *reinterpret_cast<const float4*>(&Qg[(size_t)r * HDIM + d4]);
    }

    float m_i[4], l_i[4], o[4][8];
#pragma unroll
    for (int i = 0; i < 4; i++) {
        m_i[i] = -1e30f;
        l_i[i] = 0.0f;
#pragma unroll
        for (int j = 0; j < 8; j++) o[i][j] = 0.0f;
    }

    const int nkt = qtile + 1;
    for (int kt = 0; kt < nkt; kt++) {
        const int k0 = kt * BKT;
        __syncthreads();   // previous iter's Ks/Vs/Ps fully consumed (also covers Q load)

        const float* Kg = g_K + (size_t)(b * SEQT + k0) * HDIM;
        const float* Vg = g_V + (size_t)(b * SEQT + k0) * HDIM;
#pragma unroll
        for (int s = 0; s < 8; s++) {
            int idx = tid + s * 256;
            int r   = idx >> 5;
            int d4  = (idx & 31) * 4;
            *reinterpret_cast<float4*>(&Ks[r * QS + d4]) =
                *reinterpret_cast<const float4*>(&Kg[(size_t)r * HDIM + d4]);
            *reinterpret_cast<float4*>(&Vs[r * QS + d4]) =
                *reinterpret_cast<const float4*>(&Vg[(size_t)r * HDIM + d4]);
        }
        __syncthreads();

        // S = Q K^T  (4x4 micro-tile per thread)
        float sc[4][4];
#pragma unroll
        for (int i = 0; i < 4; i++)
#pragma unroll
            for (int j = 0; j < 4; j++) sc[i][j] = 0.0f;

        for (int d = 0; d < HDIM; d++) {
            float qv[4], kv[4];
#pragma unroll
            for (int i = 0; i < 4; i++) qv[i] = Qs[(trow * 4 + i) * QS + d];
#pragma unroll
            for (int j = 0; j < 4; j++) kv[j] = Ks[(tcol * 4 + j) * QS + d];
#pragma unroll
            for (int i = 0; i < 4; i++)
#pragma unroll
                for (int j = 0; j < 4; j++) sc[i][j] += qv[i] * kv[j];
        }

        // scale + causal mask (only needed on the diagonal tile)
        const bool diag = (kt == qtile);
#pragma unroll
        for (int i = 0; i < 4; i++)
#pragma unroll
            for (int j = 0; j < 4; j++) {
                float v = sc[i][j] * scale;
                if (diag && (tcol * 4 + j) > (trow * 4 + i)) v = -1e30f;
                sc[i][j] = v;
            }

        // row max over this tile (local 4 cols, then 16-lane shuffle reduce)
        float mt[4];
#pragma unroll
        for (int i = 0; i < 4; i++)
            mt[i] = fmaxf(fmaxf(sc[i][0], sc[i][1]), fmaxf(sc[i][2], sc[i][3]));
#pragma unroll
        for (int off = 1; off < 16; off <<= 1)
#pragma unroll
            for (int i = 0; i < 4; i++)
                mt[i] = fmaxf(mt[i], __shfl_xor_sync(0xffffffffu, mt[i], off));

        float alpha[4];
#pragma unroll
        for (int i = 0; i < 4; i++) {
            float mn = fmaxf(m_i[i], mt[i]);
            alpha[i] = __expf(m_i[i] - mn);
            m_i[i]   = mn;
        }

        // p = exp(s - m), row partial sums
        float ls[4] = {0.0f, 0.0f, 0.0f, 0.0f};
#pragma unroll
        for (int i = 0; i < 4; i++)
#pragma unroll
            for (int j = 0; j < 4; j++) {
                float p = __expf(sc[i][j] - m_i[i]);
                sc[i][j] = p;
                ls[i] += p;
            }
#pragma unroll
        for (int off = 1; off < 16; off <<= 1)
#pragma unroll
            for (int i = 0; i < 4; i++)
                ls[i] += __shfl_xor_sync(0xffffffffu, ls[i], off);
#pragma unroll
        for (int i = 0; i < 4; i++) l_i[i] = l_i[i] * alpha[i] + ls[i];

        // write P tile, rescale O
#pragma unroll
        for (int i = 0; i < 4; i++)
#pragma unroll
            for (int j = 0; j < 4; j++)
                Ps[(trow * 4 + i) * SS + tcol * 4 + j] = sc[i][j];
#pragma unroll
        for (int i = 0; i < 4; i++)
#pragma unroll
            for (int j = 0; j < 8; j++) o[i][j] *= alpha[i];
        __syncthreads();

        // O += P * V
        for (int c = 0; c < BKT; c++) {
            float pv[4];
#pragma unroll
            for (int i = 0; i < 4; i++) pv[i] = Ps[(trow * 4 + i) * SS + c];
            float4 v0 = *reinterpret_cast<const float4*>(&Vs[c * QS + tcol * 8]);
            float4 v1 = *reinterpret_cast<const float4*>(&Vs[c * QS + tcol * 8 + 4]);
            float vb[8] = {v0.x, v0.y, v0.z, v0.w, v1.x, v1.y, v1.z, v1.w};
#pragma unroll
            for (int i = 0; i < 4; i++)
#pragma unroll
                for (int j = 0; j < 8; j++)
                    o[i][j] += pv[i] * vb[j];
        }
    }

    // epilogue: normalize and store
#pragma unroll
    for (int i = 0; i < 4; i++) {
        float inv = 1.0f / l_i[i];
        int row = q0 + trow * 4 + i;
        float* og = out + (size_t)(b * SEQT + row) * HDIM + tcol * 8;
        float4 r0, r1;
        r0.x = o[i][0] * inv; r0.y = o[i][1] * inv;
        r0.z = o[i][2] * inv; r0.w = o[i][3] * inv;
        r1.x = o[i][4] * inv; r1.y = o[i][5] * inv;
        r1.z = o[i][6] * inv; r1.w = o[i][7] * inv;
        *reinterpret_cast<float4*>(og)     = r0;
        *reinterpret_cast<float4*>(og + 4) = r1;
    }
}

// ---------------------------------------------------------------------------
extern "C" void kernel_launch(void* const* d_in, const int* in_sizes, int n_in,
                              void* d_out, int out_size)
{
    const float* x  = (const float*)d_in[0];
    const float* Wq = (const float*)d_in[1];
    const float* bq = (const float*)d_in[2];
    const float* Wk = (const float*)d_in[3];
    const float* bk = (const float*)d_in[4];
    const float* Wv = (const float*)d_in[5];
    const float* bv = (const float*)d_in[6];
    float* out = (float*)d_out;

    // Projections: Q/K/V = x @ W + b
    dim3 pg(BT / PBM, 1, 3);
    proj_kernel<<<pg, 256>>>(x, Wq, bq, Wk, bk, Wv, bv);

    // Attention
    cudaFuncSetAttribute(attn_kernel,
                         cudaFuncAttributeMaxDynamicSharedMemorySize, ATTN_SMEM);
    dim3 ag(SEQT / BQ, BATCH);
    attn_kernel<<<ag, 256, ATTN_SMEM>>>(out);
}

// round 4
// speedup vs baseline: 3.6915x; 3.6915x over previous
#include <cuda_runtime.h>
#include <cuda_bf16.h>

#define BATCH 8
#define SEQT 2048
#define CDIM 1024
#define HDIM 128
#define BT (BATCH * SEQT)   // 16384 tokens

// ---------------- device scratch (16B aligned) ----------------
__device__ __align__(16) __nv_bfloat16 g_xhi[BT * CDIM];
__device__ __align__(16) __nv_bfloat16 g_xlo[BT * CDIM];
__device__ __align__(16) __nv_bfloat16 g_whi[3][CDIM * HDIM];  // [c][h]
__device__ __align__(16) __nv_bfloat16 g_wlo[3][CDIM * HDIM];
__device__ __align__(16) __nv_bfloat16 g_Qhi[BT * HDIM];
__device__ __align__(16) __nv_bfloat16 g_Qlo[BT * HDIM];
__device__ __align__(16) __nv_bfloat16 g_Khi[BT * HDIM];
__device__ __align__(16) __nv_bfloat16 g_Klo[BT * HDIM];
__device__ __align__(16) __nv_bfloat16 g_Vhi[BT * HDIM];
__device__ __align__(16) __nv_bfloat16 g_Vlo[BT * HDIM];

// ---------------- helpers ----------------
__device__ __forceinline__ unsigned smem_u32(const void* p) {
    unsigned a;
    asm("{ .reg .u64 t; cvta.to.shared.u64 t, %1; cvt.u32.u64 %0, t; }"
        : "=r"(a) : "l"(p));
    return a;
}
__device__ __forceinline__ void ldsm4(unsigned* r, unsigned a) {
    asm volatile("ldmatrix.sync.aligned.m8n8.x4.shared.b16 {%0,%1,%2,%3}, [%4];"
                 : "=r"(r[0]), "=r"(r[1]), "=r"(r[2]), "=r"(r[3]) : "r"(a));
}
__device__ __forceinline__ void ldsm4t(unsigned* r, unsigned a) {
    asm volatile("ldmatrix.sync.aligned.m8n8.x4.trans.shared.b16 {%0,%1,%2,%3}, [%4];"
                 : "=r"(r[0]), "=r"(r[1]), "=r"(r[2]), "=r"(r[3]) : "r"(a));
}
__device__ __forceinline__ void mma16816(float* d, const unsigned* a, const unsigned* b) {
    asm volatile(
        "mma.sync.aligned.m16n8k16.row.col.f32.bf16.bf16.f32 "
        "{%0,%1,%2,%3}, {%4,%5,%6,%7}, {%8,%9}, {%0,%1,%2,%3};"
        : "+f"(d[0]), "+f"(d[1]), "+f"(d[2]), "+f"(d[3])
        : "r"(a[0]), "r"(a[1]), "r"(a[2]), "r"(a[3]), "r"(b[0]), "r"(b[1]));
}
// Explicit pack: 'first' goes to LOW 16 bits (memory order / fragment k-even slot)
__device__ __forceinline__ unsigned pack2(__nv_bfloat16 first, __nv_bfloat16 second) {
    return (unsigned)__bfloat16_as_ushort(first) |
           ((unsigned)__bfloat16_as_ushort(second) << 16);
}
__device__ __forceinline__ unsigned pack2f(float first, float second) {
    return pack2(__float2bfloat16(first), __float2bfloat16(second));
}

// ---------------- prep: split fp32 -> bf16 hi/lo ----------------
__global__ __launch_bounds__(256) void split_x_kernel(const float* __restrict__ x) {
    int i = blockIdx.x * 256 + threadIdx.x;            // float4 index
    float4 v = reinterpret_cast<const float4*>(x)[i];
    __nv_bfloat16 h0 = __float2bfloat16(v.x), h1 = __float2bfloat16(v.y);
    __nv_bfloat16 h2 = __float2bfloat16(v.z), h3 = __float2bfloat16(v.w);
    unsigned* hi = reinterpret_cast<unsigned*>(g_xhi);
    unsigned* lo = reinterpret_cast<unsigned*>(g_xlo);
    hi[2 * i]     = pack2(h0, h1);
    hi[2 * i + 1] = pack2(h2, h3);
    lo[2 * i]     = pack2f(v.x - __bfloat162float(h0), v.y - __bfloat162float(h1));
    lo[2 * i + 1] = pack2f(v.z - __bfloat162float(h2), v.w - __bfloat162float(h3));
}

__global__ __launch_bounds__(256) void split_w_kernel(
    const float* __restrict__ Wq, const float* __restrict__ Wk,
    const float* __restrict__ Wv) {
    int idx = blockIdx.x * 256 + threadIdx.x;          // 0 .. 3*131072-1
    int mat = idx >> 17;
    int r   = idx & 131071;
    const float* W = (mat == 0) ? Wq : (mat == 1) ? Wk : Wv;
    float v = W[r];
    __nv_bfloat16 hi = __float2bfloat16(v);
    g_whi[mat][r] = hi;
    g_wlo[mat][r] = __float2bfloat16(v - __bfloat162float(hi));
}

// ---------------- projection GEMM (mma.sync bf16, 3-term split) -----------
// CTA: 128 tokens x 128 H, one matrix per blockIdx.z. 8 warps x m16.
#define PX_S 72      // X chunk row stride (bf16 elems)
#define PW_S 136     // W chunk row stride
#define P_XH 0
#define P_XL (128 * PX_S * 2)
#define P_WH (2 * 128 * PX_S * 2)
#define P_WL (2 * 128 * PX_S * 2 + 64 * PW_S * 2)
#define P_SMEM (2 * 128 * PX_S * 2 + 2 * 64 * PW_S * 2)   // 71680 B

__global__ __launch_bounds__(256, 1) void proj_kernel(
    const float* __restrict__ bq, const float* __restrict__ bk,
    const float* __restrict__ bv) {
    extern __shared__ char smc[];
    const unsigned sb = smem_u32(smc);
    const int tid = threadIdx.x;
    const int w   = tid >> 5;
    const int l   = tid & 31;
    const int mat = blockIdx.z;
    const int m0  = blockIdx.x * 128;

    const __nv_bfloat16* Wh = g_whi[mat];
    const __nv_bfloat16* Wl = g_wlo[mat];
    const float* bias = (mat == 0) ? bq : (mat == 1) ? bk : bv;
    __nv_bfloat16* out_hi = (mat == 0) ? g_Qhi : (mat == 1) ? g_Khi : g_Vhi;
    __nv_bfloat16* out_lo = (mat == 0) ? g_Qlo : (mat == 1) ? g_Klo : g_Vlo;

    float acc[16][4];
#pragma unroll
    for (int t = 0; t < 16; t++)
#pragma unroll
        for (int r = 0; r < 4; r++) acc[t][r] = 0.0f;

    for (int ch = 0; ch < 16; ch++) {
        const int k0 = ch * 64;
        __syncthreads();
        // X tiles: 128 rows x 64 bf16
#pragma unroll
        for (int t = 0; t < 4; t++) {
            int u = tid + t * 256;
            int row = u >> 3, q = u & 7;
            *reinterpret_cast<uint4*>(smc + P_XH + (row * PX_S + q * 8) * 2) =
                *reinterpret_cast<const uint4*>(
                    g_xhi + (size_t)(m0 + row) * CDIM + k0 + q * 8);
            *reinterpret_cast<uint4*>(smc + P_XL + (row * PX_S + q * 8) * 2) =
                *reinterpret_cast<const uint4*>(
                    g_xlo + (size_t)(m0 + row) * CDIM + k0 + q * 8);
        }
        // W tiles: 64 rows x 128 bf16
#pragma unroll
        for (int t = 0; t < 4; t++) {
            int u = tid + t * 256;
            int row = u >> 4, q = u & 15;
            *reinterpret_cast<uint4*>(smc + P_WH + (row * PW_S + q * 8) * 2) =
                *reinterpret_cast<const uint4*>(Wh + (size_t)(k0 + row) * HDIM + q * 8);
            *reinterpret_cast<uint4*>(smc + P_WL + (row * PW_S + q * 8) * 2) =
                *reinterpret_cast<const uint4*>(Wl + (size_t)(k0 + row) * HDIM + q * 8);
        }
        __syncthreads();

#pragma unroll
        for (int ks = 0; ks < 4; ks++) {
            const int kk = ks * 16;
            unsigned ah[4], al[4];
            unsigned a_addr = sb + P_XH +
                ((w * 16 + (l & 15)) * PX_S + kk + 8 * (l >> 4)) * 2;
            ldsm4(ah, a_addr);
            ldsm4(al, a_addr + (P_XL - P_XH));
#pragma unroll
            for (int nt2 = 0; nt2 < 8; nt2++) {      // FIXED: full 128 cols
                unsigned bh[4], bl[4];
                unsigned b_addr = sb + P_WH +
                    ((kk + (l & 15)) * PW_S + nt2 * 16 + 8 * (l >> 4)) * 2;
                ldsm4t(bh, b_addr);
                ldsm4t(bl, b_addr + (P_WL - P_WH));
                mma16816(acc[2 * nt2],     ah, bh);
                mma16816(acc[2 * nt2 + 1], ah, bh + 2);
                mma16816(acc[2 * nt2],     al, bh);
                mma16816(acc[2 * nt2 + 1], al, bh + 2);
                mma16816(acc[2 * nt2],     ah, bl);
                mma16816(acc[2 * nt2 + 1], ah, bl + 2);
            }
        }
    }

    // epilogue: scalar bf16 hi/lo stores (unambiguous layout)
    const int r0 = m0 + w * 16 + (l >> 2);
    const int r1 = r0 + 8;
#pragma unroll
    for (int nt = 0; nt < 16; nt++) {
        int c = nt * 8 + (l & 3) * 2;
        float vals[4] = {acc[nt][0] + bias[c], acc[nt][1] + bias[c + 1],
                         acc[nt][2] + bias[c], acc[nt][3] + bias[c + 1]};
        int rows[4] = {r0, r0, r1, r1};
        int cols[4] = {c, c + 1, c, c + 1};
#pragma unroll
        for (int e = 0; e < 4; e++) {
            size_t off = (size_t)rows[e] * HDIM + cols[e];
            __nv_bfloat16 h = __float2bfloat16(vals[e]);
            out_hi[off] = h;
            out_lo[off] = __float2bfloat16(vals[e] - __bfloat162float(h));
        }
    }
}

// ---------------- flash attention (mma.sync, full hi/lo splits) -----------
// CTA: 128 q-rows, 8 warps x m16, BK=64 keys/iter. QK^T and PV both 3-term.
#define AT_S 136
#define A_QH 0
#define A_QL (128 * AT_S * 2)
#define A_KH (2 * 128 * AT_S * 2)
#define A_KL (A_KH + 64 * AT_S * 2)
#define A_VH (A_KH + 2 * 64 * AT_S * 2)
#define A_VL (A_KH + 3 * 64 * AT_S * 2)
#define A_SMEM (2 * 128 * AT_S * 2 + 4 * 64 * AT_S * 2)   // 139264 B

__global__ __launch_bounds__(256, 1) void attn_kernel(float* __restrict__ out) {
    extern __shared__ char smc[];
    const unsigned sb = smem_u32(smc);
    const int tid = threadIdx.x;
    const int w   = tid >> 5;
    const int l   = tid & 31;
    const int qt  = blockIdx.x;
    const int b   = blockIdx.y;
    const int q0  = qt * 128;
    const float scale = 0.03125f;   // 1024^-0.5

    // load Q hi/lo tiles (128 x 128 bf16 each)
#pragma unroll
    for (int t = 0; t < 8; t++) {
        int u = tid + t * 256;
        int row = u >> 4, q = u & 15;
        size_t g = (size_t)(b * SEQT + q0 + row) * HDIM + q * 8;
        unsigned so = (row * AT_S + q * 8) * 2;
        *reinterpret_cast<uint4*>(smc + A_QH + so) =
            *reinterpret_cast<const uint4*>(g_Qhi + g);
        *reinterpret_cast<uint4*>(smc + A_QL + so) =
            *reinterpret_cast<const uint4*>(g_Qlo + g);
    }

    float m0_ = -1e30f, m1_ = -1e30f, l0_ = 0.0f, l1_ = 0.0f;
    float O[16][4];
#pragma unroll
    for (int t = 0; t < 16; t++)
#pragma unroll
        for (int r = 0; r < 4; r++) O[t][r] = 0.0f;

    const int r0g = q0 + w * 16 + (l >> 2);
    const int r1g = r0g + 8;
    const int nkt = 2 * (qt + 1);

    for (int kt = 0; kt < nkt; kt++) {
        const int k0 = kt * 64;
        __syncthreads();
        // load K hi/lo + V hi/lo tiles (64 x 128 each)
#pragma unroll
        for (int t = 0; t < 4; t++) {
            int u = tid + t * 256;
            int row = u >> 4, q = u & 15;
            size_t g = (size_t)(b * SEQT + k0 + row) * HDIM + q * 8;
            unsigned so = (row * AT_S + q * 8) * 2;
            *reinterpret_cast<uint4*>(smc + A_KH + so) =
                *reinterpret_cast<const uint4*>(g_Khi + g);
            *reinterpret_cast<uint4*>(smc + A_KL + so) =
                *reinterpret_cast<const uint4*>(g_Klo + g);
            *reinterpret_cast<uint4*>(smc + A_VH + so) =
                *reinterpret_cast<const uint4*>(g_Vhi + g);
            *reinterpret_cast<uint4*>(smc + A_VL + so) =
                *reinterpret_cast<const uint4*>(g_Vlo + g);
        }
        __syncthreads();

        // ---- S = Q K^T (3-term split) ----
        float sacc[8][4];
#pragma unroll
        for (int t = 0; t < 8; t++)
#pragma unroll
            for (int r = 0; r < 4; r++) sacc[t][r] = 0.0f;

#pragma unroll
        for (int ks = 0; ks < 8; ks++) {
            const int kk = ks * 16;
            unsigned ah[4], al[4];
            unsigned a_addr = sb + A_QH +
                ((w * 16 + (l & 15)) * AT_S + kk + 8 * (l >> 4)) * 2;
            ldsm4(ah, a_addr);
            ldsm4(al, a_addr + (A_QL - A_QH));
#pragma unroll
            for (int nt2 = 0; nt2 < 4; nt2++) {
                unsigned bh[4], bl[4];
                unsigned baddr = sb + A_KH +
                    ((nt2 * 16 + ((l >> 4) << 3) + (l & 7)) * AT_S +
                     kk + 8 * ((l >> 3) & 1)) * 2;
                ldsm4(bh, baddr);
                ldsm4(bl, baddr + (A_KL - A_KH));
                mma16816(sacc[2 * nt2],     ah, bh);
                mma16816(sacc[2 * nt2 + 1], ah, bh + 2);
                mma16816(sacc[2 * nt2],     al, bh);
                mma16816(sacc[2 * nt2 + 1], al, bh + 2);
                mma16816(sacc[2 * nt2],     ah, bl);
                mma16816(sacc[2 * nt2 + 1], ah, bl + 2);
            }
        }

        // ---- softmax (fp32, online) ----
        const bool mask_it = (kt >= 2 * qt);
#pragma unroll
        for (int nt = 0; nt < 8; nt++) {
            int cg = k0 + nt * 8 + (l & 3) * 2;
            float s0 = sacc[nt][0] * scale, s1 = sacc[nt][1] * scale;
            float s2 = sacc[nt][2] * scale, s3 = sacc[nt][3] * scale;
            if (mask_it) {
                if (cg     > r0g) s0 = -1e30f;
                if (cg + 1 > r0g) s1 = -1e30f;
                if (cg     > r1g) s2 = -1e30f;
                if (cg + 1 > r1g) s3 = -1e30f;
            }
            sacc[nt][0] = s0; sacc[nt][1] = s1; sacc[nt][2] = s2; sacc[nt][3] = s3;
        }
        float mt0 = -1e30f, mt1 = -1e30f;
#pragma unroll
        for (int nt = 0; nt < 8; nt++) {
            mt0 = fmaxf(mt0, fmaxf(sacc[nt][0], sacc[nt][1]));
            mt1 = fmaxf(mt1, fmaxf(sacc[nt][2], sacc[nt][3]));
        }
        mt0 = fmaxf(mt0, __shfl_xor_sync(0xffffffffu, mt0, 1));
        mt0 = fmaxf(mt0, __shfl_xor_sync(0xffffffffu, mt0, 2));
        mt1 = fmaxf(mt1, __shfl_xor_sync(0xffffffffu, mt1, 1));
        mt1 = fmaxf(mt1, __shfl_xor_sync(0xffffffffu, mt1, 2));

        float mn0 = fmaxf(m0_, mt0), mn1 = fmaxf(m1_, mt1);
        float al0 = __expf(m0_ - mn0), al1 = __expf(m1_ - mn1);
        m0_ = mn0; m1_ = mn1;

        float ls0 = 0.0f, ls1 = 0.0f;
#pragma unroll
        for (int nt = 0; nt < 8; nt++) {
            float p0 = __expf(sacc[nt][0] - m0_);
            float p1 = __expf(sacc[nt][1] - m0_);
            float p2 = __expf(sacc[nt][2] - m1_);
            float p3 = __expf(sacc[nt][3] - m1_);
            sacc[nt][0] = p0; sacc[nt][1] = p1; sacc[nt][2] = p2; sacc[nt][3] = p3;
            ls0 += p0 + p1; ls1 += p2 + p3;
        }
        ls0 += __shfl_xor_sync(0xffffffffu, ls0, 1);
        ls0 += __shfl_xor_sync(0xffffffffu, ls0, 2);
        ls1 += __shfl_xor_sync(0xffffffffu, ls1, 1);
        ls1 += __shfl_xor_sync(0xffffffffu, ls1, 2);
        l0_ = l0_ * al0 + ls0;
        l1_ = l1_ * al1 + ls1;

#pragma unroll
        for (int t = 0; t < 16; t++) {
            O[t][0] *= al0; O[t][1] *= al0; O[t][2] *= al1; O[t][3] *= al1;
        }

        // ---- O += P V (P and V hi/lo split, 3 terms) ----
#pragma unroll
        for (int ks2 = 0; ks2 < 4; ks2++) {
            const int t0 = 2 * ks2, t1 = 2 * ks2 + 1;
            __nv_bfloat16 h[8];
            float lo[8];
#pragma unroll
            for (int e = 0; e < 4; e++) {
                h[e]      = __float2bfloat16(sacc[t0][e]);
                lo[e]     = sacc[t0][e] - __bfloat162float(h[e]);
                h[4 + e]  = __float2bfloat16(sacc[t1][e]);
                lo[4 + e] = sacc[t1][e] - __bfloat162float(h[4 + e]);
            }
            unsigned ah[4], al2[4];
            ah[0] = pack2(h[0], h[1]);   ah[1] = pack2(h[2], h[3]);
            ah[2] = pack2(h[4], h[5]);   ah[3] = pack2(h[6], h[7]);
            al2[0] = pack2f(lo[0], lo[1]); al2[1] = pack2f(lo[2], lo[3]);
            al2[2] = pack2f(lo[4], lo[5]); al2[3] = pack2f(lo[6], lo[7]);
#pragma unroll
            for (int dt2 = 0; dt2 < 8; dt2++) {
                unsigned bh[4], bl[4];
                unsigned baddr = sb + A_VH +
                    ((ks2 * 16 + (l & 15)) * AT_S + dt2 * 16 + 8 * (l >> 4)) * 2;
                ldsm4t(bh, baddr);
                ldsm4t(bl, baddr + (A_VL - A_VH));
                mma16816(O[2 * dt2],     ah,  bh);
                mma16816(O[2 * dt2 + 1], ah,  bh + 2);
                mma16816(O[2 * dt2],     ah,  bl);
                mma16816(O[2 * dt2 + 1], ah,  bl + 2);
                mma16816(O[2 * dt2],     al2, bh);
                mma16816(O[2 * dt2 + 1], al2, bh + 2);
            }
        }
    }

    // epilogue: normalize, store fp32
    float inv0 = 1.0f / l0_, inv1 = 1.0f / l1_;
#pragma unroll
    for (int dt = 0; dt < 16; dt++) {
        int c = dt * 8 + (l & 3) * 2;
        float2 v0 = make_float2(O[dt][0] * inv0, O[dt][1] * inv0);
        float2 v1 = make_float2(O[dt][2] * inv1, O[dt][3] * inv1);
        *reinterpret_cast<float2*>(out + ((size_t)b * SEQT + r0g) * HDIM + c) = v0;
        *reinterpret_cast<float2*>(out + ((size_t)b * SEQT + r1g) * HDIM + c) = v1;
    }
}

// ---------------------------------------------------------------------------
extern "C" void kernel_launch(void* const* d_in, const int* in_sizes, int n_in,
                              void* d_out, int out_size) {
    const float* x  = (const float*)d_in[0];
    const float* Wq = (const float*)d_in[1];
    const float* bq = (const float*)d_in[2];
    const float* Wk = (const float*)d_in[3];
    const float* bk = (const float*)d_in[4];
    const float* Wv = (const float*)d_in[5];
    const float* bv = (const float*)d_in[6];
    float* out = (float*)d_out;

    split_x_kernel<<<(BT * CDIM / 4) / 256, 256>>>(x);
    split_w_kernel<<<(3 * CDIM * HDIM) / 256, 256>>>(Wq, Wk, Wv);

    cudaFuncSetAttribute(proj_kernel,
                         cudaFuncAttributeMaxDynamicSharedMemorySize, P_SMEM);
    proj_kernel<<<dim3(BT / 128, 1, 3), 256, P_SMEM>>>(bq, bk, bv);

    cudaFuncSetAttribute(attn_kernel,
                         cudaFuncAttributeMaxDynamicSharedMemorySize, A_SMEM);
    attn_kernel<<<dim3(SEQT / 128, BATCH), 256, A_SMEM>>>(out);
}

// round 5
// speedup vs baseline: 4.0975x; 1.1100x over previous
#include <cuda_runtime.h>
#include <cuda_bf16.h>

#define BATCH 8
#define SEQT 2048
#define CDIM 1024
#define HDIM 128
#define BT (BATCH * SEQT)   // 16384 tokens

// ---------------- device scratch (16B aligned) ----------------
__device__ __align__(16) __nv_bfloat16 g_xhi[BT * CDIM];
__device__ __align__(16) __nv_bfloat16 g_xlo[BT * CDIM];
__device__ __align__(16) __nv_bfloat16 g_whi[3][CDIM * HDIM];  // [c][h]
__device__ __align__(16) __nv_bfloat16 g_wlo[3][CDIM * HDIM];
__device__ __align__(16) __nv_bfloat16 g_Qhi[BT * HDIM];
__device__ __align__(16) __nv_bfloat16 g_Qlo[BT * HDIM];
__device__ __align__(16) __nv_bfloat16 g_Khi[BT * HDIM];
__device__ __align__(16) __nv_bfloat16 g_Klo[BT * HDIM];
__device__ __align__(16) __nv_bfloat16 g_Vhi[BT * HDIM];
__device__ __align__(16) __nv_bfloat16 g_Vlo[BT * HDIM];

// ---------------- helpers ----------------
__device__ __forceinline__ unsigned smem_u32(const void* p) {
    unsigned a;
    asm("{ .reg .u64 t; cvta.to.shared.u64 t, %1; cvt.u32.u64 %0, t; }"
        : "=r"(a) : "l"(p));
    return a;
}
__device__ __forceinline__ void ldsm4(unsigned* r, unsigned a) {
    asm volatile("ldmatrix.sync.aligned.m8n8.x4.shared.b16 {%0,%1,%2,%3}, [%4];"
                 : "=r"(r[0]), "=r"(r[1]), "=r"(r[2]), "=r"(r[3]) : "r"(a));
}
__device__ __forceinline__ void ldsm4t(unsigned* r, unsigned a) {
    asm volatile("ldmatrix.sync.aligned.m8n8.x4.trans.shared.b16 {%0,%1,%2,%3}, [%4];"
                 : "=r"(r[0]), "=r"(r[1]), "=r"(r[2]), "=r"(r[3]) : "r"(a));
}
__device__ __forceinline__ void mma16816(float* d, const unsigned* a, const unsigned* b) {
    asm volatile(
        "mma.sync.aligned.m16n8k16.row.col.f32.bf16.bf16.f32 "
        "{%0,%1,%2,%3}, {%4,%5,%6,%7}, {%8,%9}, {%0,%1,%2,%3};"
        : "+f"(d[0]), "+f"(d[1]), "+f"(d[2]), "+f"(d[3])
        : "r"(a[0]), "r"(a[1]), "r"(a[2]), "r"(a[3]), "r"(b[0]), "r"(b[1]));
}
__device__ __forceinline__ unsigned pack2(__nv_bfloat16 first, __nv_bfloat16 second) {
    return (unsigned)__bfloat16_as_ushort(first) |
           ((unsigned)__bfloat16_as_ushort(second) << 16);
}
__device__ __forceinline__ unsigned pack2f(float first, float second) {
    return pack2(__float2bfloat16(first), __float2bfloat16(second));
}

// ---------------- prep: split fp32 -> bf16 hi/lo ----------------
__global__ __launch_bounds__(256) void split_x_kernel(const float* __restrict__ x) {
    int i = blockIdx.x * 256 + threadIdx.x;            // float4 index
    float4 v = reinterpret_cast<const float4*>(x)[i];
    __nv_bfloat16 h0 = __float2bfloat16(v.x), h1 = __float2bfloat16(v.y);
    __nv_bfloat16 h2 = __float2bfloat16(v.z), h3 = __float2bfloat16(v.w);
    unsigned* hi = reinterpret_cast<unsigned*>(g_xhi);
    unsigned* lo = reinterpret_cast<unsigned*>(g_xlo);
    hi[2 * i]     = pack2(h0, h1);
    hi[2 * i + 1] = pack2(h2, h3);
    lo[2 * i]     = pack2f(v.x - __bfloat162float(h0), v.y - __bfloat162float(h1));
    lo[2 * i + 1] = pack2f(v.z - __bfloat162float(h2), v.w - __bfloat162float(h3));
}

__global__ __launch_bounds__(256) void split_w_kernel(
    const float* __restrict__ Wq, const float* __restrict__ Wk,
    const float* __restrict__ Wv) {
    int idx = blockIdx.x * 256 + threadIdx.x;          // 0 .. 3*131072-1
    int mat = idx >> 17;
    int r   = idx & 131071;
    const float* W = (mat == 0) ? Wq : (mat == 1) ? Wk : Wv;
    float v = W[r];
    __nv_bfloat16 hi = __float2bfloat16(v);
    g_whi[mat][r] = hi;
    g_wlo[mat][r] = __float2bfloat16(v - __bfloat162float(hi));
}

// ---------------- projection GEMM (mma.sync bf16, 3-term split) -----------
// CTA: 128 tokens x 128 H, one matrix per blockIdx.z. 8 warps x m16.
#define PX_S 72      // X chunk row stride (bf16 elems)
#define PW_S 136     // W chunk row stride
#define P_XH 0
#define P_XL (128 * PX_S * 2)
#define P_WH (2 * 128 * PX_S * 2)
#define P_WL (2 * 128 * PX_S * 2 + 64 * PW_S * 2)
#define P_SMEM (2 * 128 * PX_S * 2 + 2 * 64 * PW_S * 2)   // 71680 B

__global__ __launch_bounds__(256, 1) void proj_kernel(
    const float* __restrict__ bq, const float* __restrict__ bk,
    const float* __restrict__ bv) {
    extern __shared__ char smc[];
    const unsigned sb = smem_u32(smc);
    const int tid = threadIdx.x;
    const int w   = tid >> 5;
    const int l   = tid & 31;
    const int mat = blockIdx.z;
    const int m0  = blockIdx.x * 128;

    const __nv_bfloat16* Wh = g_whi[mat];
    const __nv_bfloat16* Wl = g_wlo[mat];
    const float* bias = (mat == 0) ? bq : (mat == 1) ? bk : bv;
    __nv_bfloat16* out_hi = (mat == 0) ? g_Qhi : (mat == 1) ? g_Khi : g_Vhi;
    __nv_bfloat16* out_lo = (mat == 0) ? g_Qlo : (mat == 1) ? g_Klo : g_Vlo;

    float acc[16][4];
#pragma unroll
    for (int t = 0; t < 16; t++)
#pragma unroll
        for (int r = 0; r < 4; r++) acc[t][r] = 0.0f;

    for (int ch = 0; ch < 16; ch++) {
        const int k0 = ch * 64;
        __syncthreads();
#pragma unroll
        for (int t = 0; t < 4; t++) {
            int u = tid + t * 256;
            int row = u >> 3, q = u & 7;
            *reinterpret_cast<uint4*>(smc + P_XH + (row * PX_S + q * 8) * 2) =
                *reinterpret_cast<const uint4*>(
                    g_xhi + (size_t)(m0 + row) * CDIM + k0 + q * 8);
            *reinterpret_cast<uint4*>(smc + P_XL + (row * PX_S + q * 8) * 2) =
                *reinterpret_cast<const uint4*>(
                    g_xlo + (size_t)(m0 + row) * CDIM + k0 + q * 8);
        }
#pragma unroll
        for (int t = 0; t < 4; t++) {
            int u = tid + t * 256;
            int row = u >> 4, q = u & 15;
            *reinterpret_cast<uint4*>(smc + P_WH + (row * PW_S + q * 8) * 2) =
                *reinterpret_cast<const uint4*>(Wh + (size_t)(k0 + row) * HDIM + q * 8);
            *reinterpret_cast<uint4*>(smc + P_WL + (row * PW_S + q * 8) * 2) =
                *reinterpret_cast<const uint4*>(Wl + (size_t)(k0 + row) * HDIM + q * 8);
        }
        __syncthreads();

#pragma unroll
        for (int ks = 0; ks < 4; ks++) {
            const int kk = ks * 16;
            unsigned ah[4], al[4];
            unsigned a_addr = sb + P_XH +
                ((w * 16 + (l & 15)) * PX_S + kk + 8 * (l >> 4)) * 2;
            ldsm4(ah, a_addr);
            ldsm4(al, a_addr + (P_XL - P_XH));
#pragma unroll
            for (int nt2 = 0; nt2 < 8; nt2++) {
                unsigned bh[4], bl[4];
                unsigned b_addr = sb + P_WH +
                    ((kk + (l & 15)) * PW_S + nt2 * 16 + 8 * (l >> 4)) * 2;
                ldsm4t(bh, b_addr);
                ldsm4t(bl, b_addr + (P_WL - P_WH));
                mma16816(acc[2 * nt2],     ah, bh);
                mma16816(acc[2 * nt2 + 1], ah, bh + 2);
                mma16816(acc[2 * nt2],     al, bh);
                mma16816(acc[2 * nt2 + 1], al, bh + 2);
                mma16816(acc[2 * nt2],     ah, bl);
                mma16816(acc[2 * nt2 + 1], ah, bl + 2);
            }
        }
    }

    const int r0 = m0 + w * 16 + (l >> 2);
    const int r1 = r0 + 8;
#pragma unroll
    for (int nt = 0; nt < 16; nt++) {
        int c = nt * 8 + (l & 3) * 2;
        float vals[4] = {acc[nt][0] + bias[c], acc[nt][1] + bias[c + 1],
                         acc[nt][2] + bias[c], acc[nt][3] + bias[c + 1]};
        int rows[4] = {r0, r0, r1, r1};
        int cols[4] = {c, c + 1, c, c + 1};
#pragma unroll
        for (int e = 0; e < 4; e++) {
            size_t off = (size_t)rows[e] * HDIM + cols[e];
            __nv_bfloat16 h = __float2bfloat16(vals[e]);
            out_hi[off] = h;
            out_lo[off] = __float2bfloat16(vals[e] - __bfloat162float(h));
        }
    }
}

// ---------------- flash attention: BQ=64, 4 warps, 2 CTAs/SM --------------
#define AT_S 136
#define A_QH 0
#define A_QL (64 * AT_S * 2)
#define A_KH (2 * 64 * AT_S * 2)
#define A_KL (3 * 64 * AT_S * 2)
#define A_VH (4 * 64 * AT_S * 2)
#define A_VL (5 * 64 * AT_S * 2)
#define A_SMEM (6 * 64 * AT_S * 2)   // 104448 B -> 2 CTAs/SM

__global__ __launch_bounds__(128, 2) void attn_kernel(float* __restrict__ out) {
    extern __shared__ char smc[];
    const unsigned sb = smem_u32(smc);
    const int tid = threadIdx.x;
    const int w   = tid >> 5;          // 0..3
    const int l   = tid & 31;
    const int qt  = 31 - (blockIdx.x >> 3);   // heavy tiles launch first
    const int b   = blockIdx.x & 7;
    const int q0  = qt * 64;
    const float scale = 0.03125f;      // 1024^-0.5

    // load Q hi/lo tiles (64 x 128 bf16 each)
#pragma unroll
    for (int t = 0; t < 8; t++) {
        int u = tid + t * 128;
        int row = u >> 4, q = u & 15;
        size_t g = (size_t)(b * SEQT + q0 + row) * HDIM + q * 8;
        unsigned so = (row * AT_S + q * 8) * 2;
        *reinterpret_cast<uint4*>(smc + A_QH + so) =
            *reinterpret_cast<const uint4*>(g_Qhi + g);
        *reinterpret_cast<uint4*>(smc + A_QL + so) =
            *reinterpret_cast<const uint4*>(g_Qlo + g);
    }

    float m0_ = -1e30f, m1_ = -1e30f, l0_ = 0.0f, l1_ = 0.0f;
    float O[16][4];
#pragma unroll
    for (int t = 0; t < 16; t++)
#pragma unroll
        for (int r = 0; r < 4; r++) O[t][r] = 0.0f;

    const int r0g = q0 + w * 16 + (l >> 2);
    const int r1g = r0g + 8;
    const int nkt = qt + 1;

    for (int kt = 0; kt < nkt; kt++) {
        const int k0 = kt * 64;
        __syncthreads();
        // load K hi/lo + V hi/lo tiles (64 x 128 each)
#pragma unroll
        for (int t = 0; t < 8; t++) {
            int u = tid + t * 128;
            int row = u >> 4, q = u & 15;
            size_t g = (size_t)(b * SEQT + k0 + row) * HDIM + q * 8;
            unsigned so = (row * AT_S + q * 8) * 2;
            *reinterpret_cast<uint4*>(smc + A_KH + so) =
                *reinterpret_cast<const uint4*>(g_Khi + g);
            *reinterpret_cast<uint4*>(smc + A_KL + so) =
                *reinterpret_cast<const uint4*>(g_Klo + g);
            *reinterpret_cast<uint4*>(smc + A_VH + so) =
                *reinterpret_cast<const uint4*>(g_Vhi + g);
            *reinterpret_cast<uint4*>(smc + A_VL + so) =
                *reinterpret_cast<const uint4*>(g_Vlo + g);
        }
        __syncthreads();

        // ---- S = Q K^T (3-term split) ----
        float sacc[8][4];
#pragma unroll
        for (int t = 0; t < 8; t++)
#pragma unroll
            for (int r = 0; r < 4; r++) sacc[t][r] = 0.0f;

#pragma unroll
        for (int ks = 0; ks < 8; ks++) {
            const int kk = ks * 16;
            unsigned ah[4], al[4];
            unsigned a_addr = sb + A_QH +
                ((w * 16 + (l & 15)) * AT_S + kk + 8 * (l >> 4)) * 2;
            ldsm4(ah, a_addr);
            ldsm4(al, a_addr + (A_QL - A_QH));
#pragma unroll
            for (int nt2 = 0; nt2 < 4; nt2++) {
                unsigned bh[4], bl[4];
                unsigned baddr = sb + A_KH +
                    ((nt2 * 16 + ((l >> 4) << 3) + (l & 7)) * AT_S +
                     kk + 8 * ((l >> 3) & 1)) * 2;
                ldsm4(bh, baddr);
                ldsm4(bl, baddr + (A_KL - A_KH));
                mma16816(sacc[2 * nt2],     ah, bh);
                mma16816(sacc[2 * nt2 + 1], ah, bh + 2);
                mma16816(sacc[2 * nt2],     al, bh);
                mma16816(sacc[2 * nt2 + 1], al, bh + 2);
                mma16816(sacc[2 * nt2],     ah, bl);
                mma16816(sacc[2 * nt2 + 1], ah, bl + 2);
            }
        }

        // ---- softmax (fp32, online) ----
        const bool mask_it = (kt == qt);
#pragma unroll
        for (int nt = 0; nt < 8; nt++) {
            int cg = k0 + nt * 8 + (l & 3) * 2;
            float s0 = sacc[nt][0] * scale, s1 = sacc[nt][1] * scale;
            float s2 = sacc[nt][2] * scale, s3 = sacc[nt][3] * scale;
            if (mask_it) {
                if (cg     > r0g) s0 = -1e30f;
                if (cg + 1 > r0g) s1 = -1e30f;
                if (cg     > r1g) s2 = -1e30f;
                if (cg + 1 > r1g) s3 = -1e30f;
            }
            sacc[nt][0] = s0; sacc[nt][1] = s1; sacc[nt][2] = s2; sacc[nt][3] = s3;
        }
        float mt0 = -1e30f, mt1 = -1e30f;
#pragma unroll
        for (int nt = 0; nt < 8; nt++) {
            mt0 = fmaxf(mt0, fmaxf(sacc[nt][0], sacc[nt][1]));
            mt1 = fmaxf(mt1, fmaxf(sacc[nt][2], sacc[nt][3]));
        }
        mt0 = fmaxf(mt0, __shfl_xor_sync(0xffffffffu, mt0, 1));
        mt0 = fmaxf(mt0, __shfl_xor_sync(0xffffffffu, mt0, 2));
        mt1 = fmaxf(mt1, __shfl_xor_sync(0xffffffffu, mt1, 1));
        mt1 = fmaxf(mt1, __shfl_xor_sync(0xffffffffu, mt1, 2));

        float mn0 = fmaxf(m0_, mt0), mn1 = fmaxf(m1_, mt1);
        float al0 = __expf(m0_ - mn0), al1 = __expf(m1_ - mn1);
        m0_ = mn0; m1_ = mn1;

        float ls0 = 0.0f, ls1 = 0.0f;
#pragma unroll
        for (int nt = 0; nt < 8; nt++) {
            float p0 = __expf(sacc[nt][0] - m0_);
            float p1 = __expf(sacc[nt][1] - m0_);
            float p2 = __expf(sacc[nt][2] - m1_);
            float p3 = __expf(sacc[nt][3] - m1_);
            sacc[nt][0] = p0; sacc[nt][1] = p1; sacc[nt][2] = p2; sacc[nt][3] = p3;
            ls0 += p0 + p1; ls1 += p2 + p3;
        }
        ls0 += __shfl_xor_sync(0xffffffffu, ls0, 1);
        ls0 += __shfl_xor_sync(0xffffffffu, ls0, 2);
        ls1 += __shfl_xor_sync(0xffffffffu, ls1, 1);
        ls1 += __shfl_xor_sync(0xffffffffu, ls1, 2);
        l0_ = l0_ * al0 + ls0;
        l1_ = l1_ * al1 + ls1;

#pragma unroll
        for (int t = 0; t < 16; t++) {
            O[t][0] *= al0; O[t][1] *= al0; O[t][2] *= al1; O[t][3] *= al1;
        }

        // ---- O += P V (3-term) ----
#pragma unroll
        for (int ks2 = 0; ks2 < 4; ks2++) {
            const int t0 = 2 * ks2, t1 = 2 * ks2 + 1;
            __nv_bfloat16 h[8];
            float lo[8];
#pragma unroll
            for (int e = 0; e < 4; e++) {
                h[e]      = __float2bfloat16(sacc[t0][e]);
                lo[e]     = sacc[t0][e] - __bfloat162float(h[e]);
                h[4 + e]  = __float2bfloat16(sacc[t1][e]);
                lo[4 + e] = sacc[t1][e] - __bfloat162float(h[4 + e]);
            }
            unsigned ah[4], al2[4];
            ah[0] = pack2(h[0], h[1]);   ah[1] = pack2(h[2], h[3]);
            ah[2] = pack2(h[4], h[5]);   ah[3] = pack2(h[6], h[7]);
            al2[0] = pack2f(lo[0], lo[1]); al2[1] = pack2f(lo[2], lo[3]);
            al2[2] = pack2f(lo[4], lo[5]); al2[3] = pack2f(lo[6], lo[7]);
#pragma unroll
            for (int dt2 = 0; dt2 < 8; dt2++) {
                unsigned bh[4], bl[4];
                unsigned baddr = sb + A_VH +
                    ((ks2 * 16 + (l & 15)) * AT_S + dt2 * 16 + 8 * (l >> 4)) * 2;
                ldsm4t(bh, baddr);
                ldsm4t(bl, baddr + (A_VL - A_VH));
                mma16816(O[2 * dt2],     ah,  bh);
                mma16816(O[2 * dt2 + 1], ah,  bh + 2);
                mma16816(O[2 * dt2],     ah,  bl);
                mma16816(O[2 * dt2 + 1], ah,  bl + 2);
                mma16816(O[2 * dt2],     al2, bh);
                mma16816(O[2 * dt2 + 1], al2, bh + 2);
            }
        }
    }

    // epilogue: normalize, store fp32
    float inv0 = 1.0f / l0_, inv1 = 1.0f / l1_;
#pragma unroll
    for (int dt = 0; dt < 16; dt++) {
        int c = dt * 8 + (l & 3) * 2;
        float2 v0 = make_float2(O[dt][0] * inv0, O[dt][1] * inv0);
        float2 v1 = make_float2(O[dt][2] * inv1, O[dt][3] * inv1);
        *reinterpret_cast<float2*>(out + ((size_t)b * SEQT + r0g) * HDIM + c) = v0;
        *reinterpret_cast<float2*>(out + ((size_t)b * SEQT + r1g) * HDIM + c) = v1;
    }
}

// ---------------------------------------------------------------------------
extern "C" void kernel_launch(void* const* d_in, const int* in_sizes, int n_in,
                              void* d_out, int out_size) {
    const float* x  = (const float*)d_in[0];
    const float* Wq = (const float*)d_in[1];
    const float* bq = (const float*)d_in[2];
    const float* Wk = (const float*)d_in[3];
    const float* bk = (const float*)d_in[4];
    const float* Wv = (const float*)d_in[5];
    const float* bv = (const float*)d_in[6];
    float* out = (float*)d_out;

    split_x_kernel<<<(BT * CDIM / 4) / 256, 256>>>(x);
    split_w_kernel<<<(3 * CDIM * HDIM) / 256, 256>>>(Wq, Wk, Wv);

    cudaFuncSetAttribute(proj_kernel,
                         cudaFuncAttributeMaxDynamicSharedMemorySize, P_SMEM);
    proj_kernel<<<dim3(BT / 128, 1, 3), 256, P_SMEM>>>(bq, bk, bv);

    cudaFuncSetAttribute(attn_kernel,
                         cudaFuncAttributeMaxDynamicSharedMemorySize, A_SMEM);
    attn_kernel<<<dim3(32 * BATCH), 128, A_SMEM>>>(out);
}

// round 6
// speedup vs baseline: 4.3024x; 1.0500x over previous
#include <cuda_runtime.h>
#include <cuda_bf16.h>

#define BATCH 8
#define SEQT 2048
#define CDIM 1024
#define HDIM 128
#define BT (BATCH * SEQT)   // 16384 tokens

// ---------------- device scratch (16B aligned) ----------------
__device__ __align__(16) __nv_bfloat16 g_xhi[BT * CDIM];
__device__ __align__(16) __nv_bfloat16 g_xlo[BT * CDIM];
__device__ __align__(16) __nv_bfloat16 g_whi[3][CDIM * HDIM];  // [c][h]
__device__ __align__(16) __nv_bfloat16 g_wlo[3][CDIM * HDIM];
__device__ __align__(16) __nv_bfloat16 g_Qhi[BT * HDIM];
__device__ __align__(16) __nv_bfloat16 g_Qlo[BT * HDIM];
__device__ __align__(16) __nv_bfloat16 g_Khi[BT * HDIM];
__device__ __align__(16) __nv_bfloat16 g_Klo[BT * HDIM];
__device__ __align__(16) __nv_bfloat16 g_Vhi[BT * HDIM];
__device__ __align__(16) __nv_bfloat16 g_Vlo[BT * HDIM];

// ---------------- helpers ----------------
__device__ __forceinline__ unsigned smem_u32(const void* p) {
    unsigned a;
    asm("{ .reg .u64 t; cvta.to.shared.u64 t, %1; cvt.u32.u64 %0, t; }"
        : "=r"(a) : "l"(p));
    return a;
}
__device__ __forceinline__ void ldsm4(unsigned* r, unsigned a) {
    asm volatile("ldmatrix.sync.aligned.m8n8.x4.shared.b16 {%0,%1,%2,%3}, [%4];"
                 : "=r"(r[0]), "=r"(r[1]), "=r"(r[2]), "=r"(r[3]) : "r"(a));
}
__device__ __forceinline__ void ldsm4t(unsigned* r, unsigned a) {
    asm volatile("ldmatrix.sync.aligned.m8n8.x4.trans.shared.b16 {%0,%1,%2,%3}, [%4];"
                 : "=r"(r[0]), "=r"(r[1]), "=r"(r[2]), "=r"(r[3]) : "r"(a));
}
__device__ __forceinline__ void mma16816(float* d, const unsigned* a, const unsigned* b) {
    asm volatile(
        "mma.sync.aligned.m16n8k16.row.col.f32.bf16.bf16.f32 "
        "{%0,%1,%2,%3}, {%4,%5,%6,%7}, {%8,%9}, {%0,%1,%2,%3};"
        : "+f"(d[0]), "+f"(d[1]), "+f"(d[2]), "+f"(d[3])
        : "r"(a[0]), "r"(a[1]), "r"(a[2]), "r"(a[3]), "r"(b[0]), "r"(b[1]));
}
__device__ __forceinline__ unsigned pack2(__nv_bfloat16 first, __nv_bfloat16 second) {
    return (unsigned)__bfloat16_as_ushort(first) |
           ((unsigned)__bfloat16_as_ushort(second) << 16);
}
__device__ __forceinline__ unsigned pack2f(float first, float second) {
    return pack2(__float2bfloat16(first), __float2bfloat16(second));
}
__device__ __forceinline__ void cp16(unsigned dst, const void* src) {
    asm volatile("cp.async.cg.shared.global [%0], [%1], 16;"
                 :: "r"(dst), "l"(src));
}
__device__ __forceinline__ void cp_commit_wait() {
    asm volatile("cp.async.commit_group;");
    asm volatile("cp.async.wait_group 0;" ::: "memory");
}

// ---------------- prep: split fp32 -> bf16 hi/lo ----------------
__global__ __launch_bounds__(256) void split_x_kernel(const float* __restrict__ x) {
    int i = blockIdx.x * 256 + threadIdx.x;            // float4 index
    float4 v = reinterpret_cast<const float4*>(x)[i];
    __nv_bfloat16 h0 = __float2bfloat16(v.x), h1 = __float2bfloat16(v.y);
    __nv_bfloat16 h2 = __float2bfloat16(v.z), h3 = __float2bfloat16(v.w);
    unsigned* hi = reinterpret_cast<unsigned*>(g_xhi);
    unsigned* lo = reinterpret_cast<unsigned*>(g_xlo);
    hi[2 * i]     = pack2(h0, h1);
    hi[2 * i + 1] = pack2(h2, h3);
    lo[2 * i]     = pack2f(v.x - __bfloat162float(h0), v.y - __bfloat162float(h1));
    lo[2 * i + 1] = pack2f(v.z - __bfloat162float(h2), v.w - __bfloat162float(h3));
}

__global__ __launch_bounds__(256) void split_w_kernel(
    const float* __restrict__ Wq, const float* __restrict__ Wk,
    const float* __restrict__ Wv) {
    int idx = blockIdx.x * 256 + threadIdx.x;          // 0 .. 3*131072-1
    int mat = idx >> 17;
    int r   = idx & 131071;
    const float* W = (mat == 0) ? Wq : (mat == 1) ? Wk : Wv;
    float v = W[r];
    __nv_bfloat16 hi = __float2bfloat16(v);
    g_whi[mat][r] = hi;
    g_wlo[mat][r] = __float2bfloat16(v - __bfloat162float(hi));
}

// ---------------- projection GEMM (unchanged from R5) ---------------------
#define PX_S 72
#define PW_S 136
#define P_XH 0
#define P_XL (128 * PX_S * 2)
#define P_WH (2 * 128 * PX_S * 2)
#define P_WL (2 * 128 * PX_S * 2 + 64 * PW_S * 2)
#define P_SMEM (2 * 128 * PX_S * 2 + 2 * 64 * PW_S * 2)

__global__ __launch_bounds__(256, 1) void proj_kernel(
    const float* __restrict__ bq, const float* __restrict__ bk,
    const float* __restrict__ bv) {
    extern __shared__ char smc[];
    const unsigned sb = smem_u32(smc);
    const int tid = threadIdx.x;
    const int w   = tid >> 5;
    const int l   = tid & 31;
    const int mat = blockIdx.z;
    const int m0  = blockIdx.x * 128;

    const __nv_bfloat16* Wh = g_whi[mat];
    const __nv_bfloat16* Wl = g_wlo[mat];
    const float* bias = (mat == 0) ? bq : (mat == 1) ? bk : bv;
    __nv_bfloat16* out_hi = (mat == 0) ? g_Qhi : (mat == 1) ? g_Khi : g_Vhi;
    __nv_bfloat16* out_lo = (mat == 0) ? g_Qlo : (mat == 1) ? g_Klo : g_Vlo;

    float acc[16][4];
#pragma unroll
    for (int t = 0; t < 16; t++)
#pragma unroll
        for (int r = 0; r < 4; r++) acc[t][r] = 0.0f;

    for (int ch = 0; ch < 16; ch++) {
        const int k0 = ch * 64;
        __syncthreads();
#pragma unroll
        for (int t = 0; t < 4; t++) {
            int u = tid + t * 256;
            int row = u >> 3, q = u & 7;
            *reinterpret_cast<uint4*>(smc + P_XH + (row * PX_S + q * 8) * 2) =
                *reinterpret_cast<const uint4*>(
                    g_xhi + (size_t)(m0 + row) * CDIM + k0 + q * 8);
            *reinterpret_cast<uint4*>(smc + P_XL + (row * PX_S + q * 8) * 2) =
                *reinterpret_cast<const uint4*>(
                    g_xlo + (size_t)(m0 + row) * CDIM + k0 + q * 8);
        }
#pragma unroll
        for (int t = 0; t < 4; t++) {
            int u = tid + t * 256;
            int row = u >> 4, q = u & 15;
            *reinterpret_cast<uint4*>(smc + P_WH + (row * PW_S + q * 8) * 2) =
                *reinterpret_cast<const uint4*>(Wh + (size_t)(k0 + row) * HDIM + q * 8);
            *reinterpret_cast<uint4*>(smc + P_WL + (row * PW_S + q * 8) * 2) =
                *reinterpret_cast<const uint4*>(Wl + (size_t)(k0 + row) * HDIM + q * 8);
        }
        __syncthreads();

#pragma unroll
        for (int ks = 0; ks < 4; ks++) {
            const int kk = ks * 16;
            unsigned ah[4], al[4];
            unsigned a_addr = sb + P_XH +
                ((w * 16 + (l & 15)) * PX_S + kk + 8 * (l >> 4)) * 2;
            ldsm4(ah, a_addr);
            ldsm4(al, a_addr + (P_XL - P_XH));
#pragma unroll
            for (int nt2 = 0; nt2 < 8; nt2++) {
                unsigned bh[4], bl[4];
                unsigned b_addr = sb + P_WH +
                    ((kk + (l & 15)) * PW_S + nt2 * 16 + 8 * (l >> 4)) * 2;
                ldsm4t(bh, b_addr);
                ldsm4t(bl, b_addr + (P_WL - P_WH));
                mma16816(acc[2 * nt2],     ah, bh);
                mma16816(acc[2 * nt2 + 1], ah, bh + 2);
                mma16816(acc[2 * nt2],     al, bh);
                mma16816(acc[2 * nt2 + 1], al, bh + 2);
                mma16816(acc[2 * nt2],     ah, bl);
                mma16816(acc[2 * nt2 + 1], ah, bl + 2);
            }
        }
    }

    const int r0 = m0 + w * 16 + (l >> 2);
    const int r1 = r0 + 8;
#pragma unroll
    for (int nt = 0; nt < 16; nt++) {
        int c = nt * 8 + (l & 3) * 2;
        float vals[4] = {acc[nt][0] + bias[c], acc[nt][1] + bias[c + 1],
                         acc[nt][2] + bias[c], acc[nt][3] + bias[c + 1]};
        int rows[4] = {r0, r0, r1, r1};
        int cols[4] = {c, c + 1, c, c + 1};
#pragma unroll
        for (int e = 0; e < 4; e++) {
            size_t off = (size_t)rows[e] * HDIM + cols[e];
            __nv_bfloat16 h = __float2bfloat16(vals[e]);
            out_hi[off] = h;
            out_lo[off] = __float2bfloat16(vals[e] - __bfloat162float(h));
        }
    }
}

// ---------------- flash attention: BQ=64, 8 warps (4m x 2n), 2 CTAs/SM ----
// XOR-swizzled smem, no padding. 16B-unit swizzle: unit ^= (row & 7).
#define S_QH 0
#define S_QL 16384
#define S_KH 32768
#define S_KL 49152
#define S_VH 65536
#define S_VL 81920
#define S_PH 98304
#define S_PL 106496
#define A_SMEM 114688
// byte offset inside a 256B-row tile (128 bf16/row)
#define SWB(row, unit) (((row) << 8) + ((((unit) ^ ((row) & 7))) << 4))
// byte offset inside a 128B-row tile (64 bf16/row)
#define SWP(row, unit) (((row) << 7) + ((((unit) ^ ((row) & 7))) << 4))

__global__ __launch_bounds__(256, 2) void attn_kernel(float* __restrict__ out) {
    extern __shared__ char smc[];
    const unsigned sb = smem_u32(smc);
    const int tid = threadIdx.x;
    const int w   = tid >> 5;          // 0..7
    const int l   = tid & 31;
    const int wi  = w >> 1;            // m-block 0..3
    const int wj  = w & 1;             // n-half 0..1
    const int mi  = wi * 16;
    const int qt  = 31 - (blockIdx.x >> 3);   // heavy tiles first
    const int b   = blockIdx.x & 7;
    const int q0  = qt * 64;
    const float scale = 0.03125f;      // 1024^-0.5

    // prologue: Q hi/lo tiles (64 x 128 bf16) via cp.async
#pragma unroll
    for (int t = 0; t < 4; t++) {
        int u = tid + t * 256;         // 0..1023
        int row = u >> 4, q = u & 15;
        const __nv_bfloat16* sh = g_Qhi + (size_t)(b * SEQT + q0 + row) * HDIM + q * 8;
        const __nv_bfloat16* sl = g_Qlo + (size_t)(b * SEQT + q0 + row) * HDIM + q * 8;
        cp16(sb + S_QH + SWB(row, q), sh);
        cp16(sb + S_QL + SWB(row, q), sl);
    }
    asm volatile("cp.async.commit_group;");

    float m0_ = -1e30f, m1_ = -1e30f, l0_ = 0.0f, l1_ = 0.0f;
    float O[8][4];
#pragma unroll
    for (int t = 0; t < 8; t++)
#pragma unroll
        for (int r = 0; r < 4; r++) O[t][r] = 0.0f;

    const int row0 = mi + (l >> 2);    // row within CTA tile
    const int row1 = row0 + 8;
    const int r0g  = q0 + row0;        // global q row
    const int r1g  = r0g + 8;
    const int nkt  = qt + 1;

    for (int kt = 0; kt < nkt; kt++) {
        const int k0 = kt * 64;
        __syncthreads();   // (1) prev iter's smem reads complete
        // K/V hi/lo tiles via cp.async (64 x 128 each)
#pragma unroll
        for (int t = 0; t < 4; t++) {
            int u = tid + t * 256;
            int row = u >> 4, q = u & 15;
            size_t g = (size_t)(b * SEQT + k0 + row) * HDIM + q * 8;
            unsigned so = SWB(row, q);
            cp16(sb + S_KH + so, g_Khi + g);
            cp16(sb + S_KL + so, g_Klo + g);
            cp16(sb + S_VH + so, g_Vhi + g);
            cp16(sb + S_VL + so, g_Vlo + g);
        }
        cp_commit_wait();
        __syncthreads();   // (2) K/V (+Q on iter 0) visible

        // ---- S = Q K^T (3-term), warp covers rows mi..mi+15, keys 32*wj.. ----
        float sacc[4][4];
#pragma unroll
        for (int t = 0; t < 4; t++)
#pragma unroll
            for (int r = 0; r < 4; r++) sacc[t][r] = 0.0f;

#pragma unroll
        for (int ks = 0; ks < 8; ks++) {
            unsigned ah[4], al[4];
            unsigned a_off = SWB(mi + (l & 15), ks * 2 + (l >> 4));
            ldsm4(ah, sb + S_QH + a_off);
            ldsm4(al, sb + S_QL + a_off);
#pragma unroll
            for (int nt2 = 0; nt2 < 2; nt2++) {
                unsigned bh[4], bl[4];
                int brow = 32 * wj + nt2 * 16 + ((l >> 4) << 3) + (l & 7);
                unsigned b_off = SWB(brow, ks * 2 + ((l >> 3) & 1));
                ldsm4(bh, sb + S_KH + b_off);
                ldsm4(bl, sb + S_KL + b_off);
                mma16816(sacc[2 * nt2],     ah, bh);
                mma16816(sacc[2 * nt2 + 1], ah, bh + 2);
                mma16816(sacc[2 * nt2],     al, bh);
                mma16816(sacc[2 * nt2 + 1], al, bh + 2);
                mma16816(sacc[2 * nt2],     ah, bl);
                mma16816(sacc[2 * nt2 + 1], ah, bl + 2);
            }
        }

        // ---- local softmax (this warp's 32 cols) ----
        const bool mask_it = (kt == qt);
#pragma unroll
        for (int nt = 0; nt < 4; nt++) {
            int cg = k0 + 32 * wj + nt * 8 + (l & 3) * 2;
            float s0 = sacc[nt][0] * scale, s1 = sacc[nt][1] * scale;
            float s2 = sacc[nt][2] * scale, s3 = sacc[nt][3] * scale;
            if (mask_it) {
                if (cg     > r0g) s0 = -1e30f;
                if (cg + 1 > r0g) s1 = -1e30f;
                if (cg     > r1g) s2 = -1e30f;
                if (cg + 1 > r1g) s3 = -1e30f;
            }
            sacc[nt][0] = s0; sacc[nt][1] = s1; sacc[nt][2] = s2; sacc[nt][3] = s3;
        }
        float mt0 = -1e30f, mt1 = -1e30f;
#pragma unroll
        for (int nt = 0; nt < 4; nt++) {
            mt0 = fmaxf(mt0, fmaxf(sacc[nt][0], sacc[nt][1]));
            mt1 = fmaxf(mt1, fmaxf(sacc[nt][2], sacc[nt][3]));
        }
        mt0 = fmaxf(mt0, __shfl_xor_sync(0xffffffffu, mt0, 1));
        mt0 = fmaxf(mt0, __shfl_xor_sync(0xffffffffu, mt0, 2));
        mt1 = fmaxf(mt1, __shfl_xor_sync(0xffffffffu, mt1, 1));
        mt1 = fmaxf(mt1, __shfl_xor_sync(0xffffffffu, mt1, 2));

        // pl = exp(s - mt_local), local sums
        float ls0 = 0.0f, ls1 = 0.0f;
#pragma unroll
        for (int nt = 0; nt < 4; nt++) {
            float p0 = __expf(sacc[nt][0] - mt0);
            float p1 = __expf(sacc[nt][1] - mt0);
            float p2 = __expf(sacc[nt][2] - mt1);
            float p3 = __expf(sacc[nt][3] - mt1);
            sacc[nt][0] = p0; sacc[nt][1] = p1; sacc[nt][2] = p2; sacc[nt][3] = p3;
            ls0 += p0 + p1; ls1 += p2 + p3;
        }
        ls0 += __shfl_xor_sync(0xffffffffu, ls0, 1);
        ls0 += __shfl_xor_sync(0xffffffffu, ls0, 2);
        ls1 += __shfl_xor_sync(0xffffffffu, ls1, 1);
        ls1 += __shfl_xor_sync(0xffffffffu, ls1, 2);

        __syncthreads();   // (3) all K reads done -> K region reusable as xbuf
        // xbuf: float4 per row at S_KH: {mt_j0, ls_j0, mt_j1, ls_j1}
        if ((l & 3) == 0) {
            *reinterpret_cast<float2*>(smc + S_KH + row0 * 16 + 8 * wj) =
                make_float2(mt0, ls0);
            *reinterpret_cast<float2*>(smc + S_KH + row1 * 16 + 8 * wj) =
                make_float2(mt1, ls1);
        }
        __syncthreads();   // (4) partials visible

        float4 x0 = *reinterpret_cast<const float4*>(smc + S_KH + row0 * 16);
        float4 x1 = *reinterpret_cast<const float4*>(smc + S_KH + row1 * 16);

        float mn0 = fmaxf(m0_, fmaxf(x0.x, x0.z));
        float mn1 = fmaxf(m1_, fmaxf(x1.x, x1.z));
        float al0 = __expf(m0_ - mn0), al1 = __expf(m1_ - mn1);
        float f00 = __expf(x0.x - mn0), f01 = __expf(x0.z - mn0);
        float f10 = __expf(x1.x - mn1), f11 = __expf(x1.z - mn1);
        l0_ = l0_ * al0 + x0.y * f00 + x0.w * f01;
        l1_ = l1_ * al1 + x1.y * f10 + x1.w * f11;
        m0_ = mn0; m1_ = mn1;
        float fme0 = wj ? f01 : f00;
        float fme1 = wj ? f11 : f10;

#pragma unroll
        for (int t = 0; t < 8; t++) {
            O[t][0] *= al0; O[t][1] *= al0; O[t][2] *= al1; O[t][3] *= al1;
        }

        // store P hi/lo (swizzled 64x64 bf16 tiles)
#pragma unroll
        for (int nt = 0; nt < 4; nt++) {
            float p00 = sacc[nt][0] * fme0, p01 = sacc[nt][1] * fme0;
            float p10 = sacc[nt][2] * fme1, p11 = sacc[nt][3] * fme1;
            __nv_bfloat16 h00 = __float2bfloat16(p00), h01 = __float2bfloat16(p01);
            __nv_bfloat16 h10 = __float2bfloat16(p10), h11 = __float2bfloat16(p11);
            int unit = 4 * wj + nt;
            unsigned o0 = SWP(row0, unit) + (l & 3) * 4;
            unsigned o1 = SWP(row1, unit) + (l & 3) * 4;
            *reinterpret_cast<unsigned*>(smc + S_PH + o0) = pack2(h00, h01);
            *reinterpret_cast<unsigned*>(smc + S_PH + o1) = pack2(h10, h11);
            *reinterpret_cast<unsigned*>(smc + S_PL + o0) =
                pack2f(p00 - __bfloat162float(h00), p01 - __bfloat162float(h01));
            *reinterpret_cast<unsigned*>(smc + S_PL + o1) =
                pack2f(p10 - __bfloat162float(h10), p11 - __bfloat162float(h11));
        }
        __syncthreads();   // (5) P tiles visible

        // ---- O += P V (3-term), warp covers rows mi.., dims 64*wj.. ----
#pragma unroll
        for (int ks2 = 0; ks2 < 4; ks2++) {
            unsigned ph[4], pl2[4];
            unsigned p_off = SWP(mi + (l & 15), ks2 * 2 + (l >> 4));
            ldsm4(ph,  sb + S_PH + p_off);
            ldsm4(pl2, sb + S_PL + p_off);
#pragma unroll
            for (int dt2 = 0; dt2 < 4; dt2++) {
                unsigned vh[4], vl[4];
                int vrow = ks2 * 16 + (l & 15);
                unsigned v_off = SWB(vrow, 8 * wj + dt2 * 2 + (l >> 4));
                ldsm4t(vh, sb + S_VH + v_off);
                ldsm4t(vl, sb + S_VL + v_off);
                mma16816(O[2 * dt2],     ph,  vh);
                mma16816(O[2 * dt2 + 1], ph,  vh + 2);
                mma16816(O[2 * dt2],     ph,  vl);
                mma16816(O[2 * dt2 + 1], ph,  vl + 2);
                mma16816(O[2 * dt2],     pl2, vh);
                mma16816(O[2 * dt2 + 1], pl2, vh + 2);
            }
        }
    }

    // epilogue: normalize, store fp32
    float inv0 = 1.0f / l0_, inv1 = 1.0f / l1_;
#pragma unroll
    for (int dt = 0; dt < 8; dt++) {
        int c = 64 * wj + dt * 8 + (l & 3) * 2;
        float2 v0 = make_float2(O[dt][0] * inv0, O[dt][1] * inv0);
        float2 v1 = make_float2(O[dt][2] * inv1, O[dt][3] * inv1);
        *reinterpret_cast<float2*>(out + ((size_t)b * SEQT + r0g) * HDIM + c) = v0;
        *reinterpret_cast<float2*>(out + ((size_t)b * SEQT + r1g) * HDIM + c) = v1;
    }
}

// ---------------------------------------------------------------------------
extern "C" void kernel_launch(void* const* d_in, const int* in_sizes, int n_in,
                              void* d_out, int out_size) {
    const float* x  = (const float*)d_in[0];
    const float* Wq = (const float*)d_in[1];
    const float* bq = (const float*)d_in[2];
    const float* Wk = (const float*)d_in[3];
    const float* bk = (const float*)d_in[4];
    const float* Wv = (const float*)d_in[5];
    const float* bv = (const float*)d_in[6];
    float* out = (float*)d_out;

    split_x_kernel<<<(BT * CDIM / 4) / 256, 256>>>(x);
    split_w_kernel<<<(3 * CDIM * HDIM) / 256, 256>>>(Wq, Wk, Wv);

    cudaFuncSetAttribute(proj_kernel,
                         cudaFuncAttributeMaxDynamicSharedMemorySize, P_SMEM);
    proj_kernel<<<dim3(BT / 128, 1, 3), 256, P_SMEM>>>(bq, bk, bv);

    cudaFuncSetAttribute(attn_kernel,
                         cudaFuncAttributeMaxDynamicSharedMemorySize, A_SMEM);
    attn_kernel<<<dim3(32 * BATCH), 256, A_SMEM>>>(out);
}

// round 7
// speedup vs baseline: 4.6027x; 1.0698x over previous
#include <cuda_runtime.h>
#include <cuda_bf16.h>

#define BATCH 8
#define SEQT 2048
#define CDIM 1024
#define HDIM 128
#define BT (BATCH * SEQT)   // 16384 tokens

// ---------------- device scratch (16B aligned) ----------------
__device__ __align__(16) __nv_bfloat16 g_xhi[BT * CDIM];
__device__ __align__(16) __nv_bfloat16 g_xlo[BT * CDIM];
__device__ __align__(16) __nv_bfloat16 g_whi[3][CDIM * HDIM];  // [c][h]
__device__ __align__(16) __nv_bfloat16 g_wlo[3][CDIM * HDIM];
__device__ __align__(16) __nv_bfloat16 g_Qhi[BT * HDIM];
__device__ __align__(16) __nv_bfloat16 g_Qlo[BT * HDIM];
__device__ __align__(16) __nv_bfloat16 g_Khi[BT * HDIM];
__device__ __align__(16) __nv_bfloat16 g_Klo[BT * HDIM];
__device__ __align__(16) __nv_bfloat16 g_Vhi[BT * HDIM];
__device__ __align__(16) __nv_bfloat16 g_Vlo[BT * HDIM];

// ---------------- helpers ----------------
__device__ __forceinline__ unsigned smem_u32(const void* p) {
    unsigned a;
    asm("{ .reg .u64 t; cvta.to.shared.u64 t, %1; cvt.u32.u64 %0, t; }"
        : "=r"(a) : "l"(p));
    return a;
}
__device__ __forceinline__ void ldsm4(unsigned* r, unsigned a) {
    asm volatile("ldmatrix.sync.aligned.m8n8.x4.shared.b16 {%0,%1,%2,%3}, [%4];"
                 : "=r"(r[0]), "=r"(r[1]), "=r"(r[2]), "=r"(r[3]) : "r"(a));
}
__device__ __forceinline__ void ldsm4t(unsigned* r, unsigned a) {
    asm volatile("ldmatrix.sync.aligned.m8n8.x4.trans.shared.b16 {%0,%1,%2,%3}, [%4];"
                 : "=r"(r[0]), "=r"(r[1]), "=r"(r[2]), "=r"(r[3]) : "r"(a));
}
__device__ __forceinline__ void mma16816(float* d, const unsigned* a, const unsigned* b) {
    asm volatile(
        "mma.sync.aligned.m16n8k16.row.col.f32.bf16.bf16.f32 "
        "{%0,%1,%2,%3}, {%4,%5,%6,%7}, {%8,%9}, {%0,%1,%2,%3};"
        : "+f"(d[0]), "+f"(d[1]), "+f"(d[2]), "+f"(d[3])
        : "r"(a[0]), "r"(a[1]), "r"(a[2]), "r"(a[3]), "r"(b[0]), "r"(b[1]));
}
__device__ __forceinline__ unsigned pack2(__nv_bfloat16 first, __nv_bfloat16 second) {
    return (unsigned)__bfloat16_as_ushort(first) |
           ((unsigned)__bfloat16_as_ushort(second) << 16);
}
__device__ __forceinline__ unsigned pack2f(float first, float second) {
    return pack2(__float2bfloat16(first), __float2bfloat16(second));
}
__device__ __forceinline__ void cp16(unsigned dst, const void* src) {
    asm volatile("cp.async.cg.shared.global [%0], [%1], 16;"
                 :: "r"(dst), "l"(src));
}
#define CP_COMMIT() asm volatile("cp.async.commit_group;")
#define CP_WAIT0()  asm volatile("cp.async.wait_group 0;" ::: "memory")
#define CP_WAIT1()  asm volatile("cp.async.wait_group 1;" ::: "memory")

// ---------------- prep: split fp32 -> bf16 hi/lo ----------------
__global__ __launch_bounds__(256) void split_x_kernel(const float* __restrict__ x) {
    int i = blockIdx.x * 256 + threadIdx.x;            // float4 index
    float4 v = reinterpret_cast<const float4*>(x)[i];
    __nv_bfloat16 h0 = __float2bfloat16(v.x), h1 = __float2bfloat16(v.y);
    __nv_bfloat16 h2 = __float2bfloat16(v.z), h3 = __float2bfloat16(v.w);
    unsigned* hi = reinterpret_cast<unsigned*>(g_xhi);
    unsigned* lo = reinterpret_cast<unsigned*>(g_xlo);
    hi[2 * i]     = pack2(h0, h1);
    hi[2 * i + 1] = pack2(h2, h3);
    lo[2 * i]     = pack2f(v.x - __bfloat162float(h0), v.y - __bfloat162float(h1));
    lo[2 * i + 1] = pack2f(v.z - __bfloat162float(h2), v.w - __bfloat162float(h3));
}

__global__ __launch_bounds__(256) void split_w_kernel(
    const float* __restrict__ Wq, const float* __restrict__ Wk,
    const float* __restrict__ Wv) {
    int idx = blockIdx.x * 256 + threadIdx.x;          // 0 .. 3*131072-1
    int mat = idx >> 17;
    int r   = idx & 131071;
    const float* W = (mat == 0) ? Wq : (mat == 1) ? Wk : Wv;
    float v = W[r];
    __nv_bfloat16 hi = __float2bfloat16(v);
    g_whi[mat][r] = hi;
    g_wlo[mat][r] = __float2bfloat16(v - __bfloat162float(hi));
}

// ---------------- projection GEMM: 2-stage cp.async pipeline --------------
#define PX_S 72
#define PW_S 136
#define PSTG  71680
#define PP_XH 0
#define PP_XL 18432
#define PP_WH 36864
#define PP_WL 54272
#define P_SMEM (2 * PSTG)   // 143360 B, 1 CTA/SM

__global__ __launch_bounds__(256, 1) void proj_kernel(
    const float* __restrict__ bq, const float* __restrict__ bk,
    const float* __restrict__ bv) {
    extern __shared__ char smc[];
    const unsigned sb = smem_u32(smc);
    const int tid = threadIdx.x;
    const int w   = tid >> 5;
    const int l   = tid & 31;
    const int mat = blockIdx.z;
    const int m0  = blockIdx.x * 128;

    const __nv_bfloat16* Wh = g_whi[mat];
    const __nv_bfloat16* Wl = g_wlo[mat];
    const float* bias = (mat == 0) ? bq : (mat == 1) ? bk : bv;
    __nv_bfloat16* out_hi = (mat == 0) ? g_Qhi : (mat == 1) ? g_Khi : g_Vhi;
    __nv_bfloat16* out_lo = (mat == 0) ? g_Qlo : (mat == 1) ? g_Klo : g_Vlo;

    auto issue_loads = [&](int ch, int s) {
        const int k0 = ch * 64;
        const unsigned st = sb + s * PSTG;
#pragma unroll
        for (int t = 0; t < 4; t++) {
            int u = tid + t * 256;
            int row = u >> 3, q = u & 7;
            unsigned so = (unsigned)((row * PX_S + q * 8) * 2);
            cp16(st + PP_XH + so, g_xhi + (size_t)(m0 + row) * CDIM + k0 + q * 8);
            cp16(st + PP_XL + so, g_xlo + (size_t)(m0 + row) * CDIM + k0 + q * 8);
        }
#pragma unroll
        for (int t = 0; t < 4; t++) {
            int u = tid + t * 256;
            int row = u >> 4, q = u & 15;
            unsigned so = (unsigned)((row * PW_S + q * 8) * 2);
            cp16(st + PP_WH + so, Wh + (size_t)(k0 + row) * HDIM + q * 8);
            cp16(st + PP_WL + so, Wl + (size_t)(k0 + row) * HDIM + q * 8);
        }
        CP_COMMIT();
    };

    float acc[16][4];
#pragma unroll
    for (int t = 0; t < 16; t++)
#pragma unroll
        for (int r = 0; r < 4; r++) acc[t][r] = 0.0f;

    issue_loads(0, 0);

    for (int ch = 0; ch < 16; ch++) {
        const int s = ch & 1;
        if (ch < 15) {
            issue_loads(ch + 1, s ^ 1);
            CP_WAIT1();
        } else {
            CP_WAIT0();
        }
        __syncthreads();   // stage s data visible to all warps

        const unsigned st = sb + s * PSTG;
#pragma unroll
        for (int ks = 0; ks < 4; ks++) {
            const int kk = ks * 16;
            unsigned ah[4], al[4];
            unsigned a_addr = st + PP_XH +
                ((w * 16 + (l & 15)) * PX_S + kk + 8 * (l >> 4)) * 2;
            ldsm4(ah, a_addr);
            ldsm4(al, a_addr + (PP_XL - PP_XH));
#pragma unroll
            for (int nt2 = 0; nt2 < 8; nt2++) {
                unsigned bh[4], bl[4];
                unsigned b_addr = st + PP_WH +
                    ((kk + (l & 15)) * PW_S + nt2 * 16 + 8 * (l >> 4)) * 2;
                ldsm4t(bh, b_addr);
                ldsm4t(bl, b_addr + (PP_WL - PP_WH));
                mma16816(acc[2 * nt2],     ah, bh);
                mma16816(acc[2 * nt2 + 1], ah, bh + 2);
                mma16816(acc[2 * nt2],     al, bh);
                mma16816(acc[2 * nt2 + 1], al, bh + 2);
                mma16816(acc[2 * nt2],     ah, bl);
                mma16816(acc[2 * nt2 + 1], ah, bl + 2);
            }
        }
        __syncthreads();   // all warps done with stage s before overwrite
    }

    const int r0 = m0 + w * 16 + (l >> 2);
    const int r1 = r0 + 8;
#pragma unroll
    for (int nt = 0; nt < 16; nt++) {
        int c = nt * 8 + (l & 3) * 2;
        float vals[4] = {acc[nt][0] + bias[c], acc[nt][1] + bias[c + 1],
                         acc[nt][2] + bias[c], acc[nt][3] + bias[c + 1]};
        int rows[4] = {r0, r0, r1, r1};
        int cols[4] = {c, c + 1, c, c + 1};
#pragma unroll
        for (int e = 0; e < 4; e++) {
            size_t off = (size_t)rows[e] * HDIM + cols[e];
            __nv_bfloat16 h = __float2bfloat16(vals[e]);
            out_hi[off] = h;
            out_lo[off] = __float2bfloat16(vals[e] - __bfloat162float(h));
        }
    }
}

// ---------------- flash attention: BQ=64, 8 warps, 2 CTAs/SM, pipelined ---
#define S_QH 0
#define S_QL 16384
#define S_KH 32768
#define S_KL 49152
#define S_VH 65536
#define S_VL 81920
#define S_PH 98304
#define S_PL 106496
#define A_SMEM 114688
#define SWB(row, unit) (((row) << 8) + ((((unit) ^ ((row) & 7))) << 4))
#define SWP(row, unit) (((row) << 7) + ((((unit) ^ ((row) & 7))) << 4))

__global__ __launch_bounds__(256, 2) void attn_kernel(float* __restrict__ out) {
    extern __shared__ char smc[];
    const unsigned sb = smem_u32(smc);
    const int tid = threadIdx.x;
    const int w   = tid >> 5;          // 0..7
    const int l   = tid & 31;
    const int wi  = w >> 1;            // m-block 0..3
    const int wj  = w & 1;             // n-half 0..1
    const int mi  = wi * 16;
    const int qt  = 31 - (blockIdx.x >> 3);   // heavy tiles first
    const int b   = blockIdx.x & 7;
    const int q0  = qt * 64;
    const float scale = 0.03125f;      // 1024^-0.5

    const int lrow = (tid >> 4);             // 0..15 (+16r per t)
    const int lq   = tid & 15;

    // prologue: Q + K(0) as group 0, V(0) as group 1
#pragma unroll
    for (int t = 0; t < 4; t++) {
        int row = lrow + t * 16;
        size_t g = (size_t)(b * SEQT + q0 + row) * HDIM + lq * 8;
        cp16(sb + S_QH + SWB(row, lq), g_Qhi + g);
        cp16(sb + S_QL + SWB(row, lq), g_Qlo + g);
    }
#pragma unroll
    for (int t = 0; t < 4; t++) {
        int row = lrow + t * 16;
        size_t g = (size_t)(b * SEQT + row) * HDIM + lq * 8;
        cp16(sb + S_KH + SWB(row, lq), g_Khi + g);
        cp16(sb + S_KL + SWB(row, lq), g_Klo + g);
    }
    CP_COMMIT();
#pragma unroll
    for (int t = 0; t < 4; t++) {
        int row = lrow + t * 16;
        size_t g = (size_t)(b * SEQT + row) * HDIM + lq * 8;
        cp16(sb + S_VH + SWB(row, lq), g_Vhi + g);
        cp16(sb + S_VL + SWB(row, lq), g_Vlo + g);
    }
    CP_COMMIT();

    float m0_ = -1e30f, m1_ = -1e30f, l0_ = 0.0f, l1_ = 0.0f;
    float O[8][4];
#pragma unroll
    for (int t = 0; t < 8; t++)
#pragma unroll
        for (int r = 0; r < 4; r++) O[t][r] = 0.0f;

    const int row0 = mi + (l >> 2);
    const int row1 = row0 + 8;
    const int r0g  = q0 + row0;
    const int r1g  = r0g + 8;
    const int nkt  = qt + 1;

    for (int kt = 0; kt < nkt; kt++) {
        const int k0 = kt * 64;
        CP_WAIT1();        // K(kt) (and Q) landed; V(kt) may still fly
        __syncthreads();   // (2) cross-thread visibility of K

        // ---- S = Q K^T (3-term) ----
        float sacc[4][4];
#pragma unroll
        for (int t = 0; t < 4; t++)
#pragma unroll
            for (int r = 0; r < 4; r++) sacc[t][r] = 0.0f;

#pragma unroll
        for (int ks = 0; ks < 8; ks++) {
            unsigned ah[4], al[4];
            unsigned a_off = SWB(mi + (l & 15), ks * 2 + (l >> 4));
            ldsm4(ah, sb + S_QH + a_off);
            ldsm4(al, sb + S_QL + a_off);
#pragma unroll
            for (int nt2 = 0; nt2 < 2; nt2++) {
                unsigned bh[4], bl[4];
                int brow = 32 * wj + nt2 * 16 + ((l >> 4) << 3) + (l & 7);
                unsigned b_off = SWB(brow, ks * 2 + ((l >> 3) & 1));
                ldsm4(bh, sb + S_KH + b_off);
                ldsm4(bl, sb + S_KL + b_off);
                mma16816(sacc[2 * nt2],     ah, bh);
                mma16816(sacc[2 * nt2 + 1], ah, bh + 2);
                mma16816(sacc[2 * nt2],     al, bh);
                mma16816(sacc[2 * nt2 + 1], al, bh + 2);
                mma16816(sacc[2 * nt2],     ah, bl);
                mma16816(sacc[2 * nt2 + 1], ah, bl + 2);
            }
        }

        // ---- local softmax (this warp's 32 cols) ----
        const bool mask_it = (kt == qt);
#pragma unroll
        for (int nt = 0; nt < 4; nt++) {
            int cg = k0 + 32 * wj + nt * 8 + (l & 3) * 2;
            float s0 = sacc[nt][0] * scale, s1 = sacc[nt][1] * scale;
            float s2 = sacc[nt][2] * scale, s3 = sacc[nt][3] * scale;
            if (mask_it) {
                if (cg     > r0g) s0 = -1e30f;
                if (cg + 1 > r0g) s1 = -1e30f;
                if (cg     > r1g) s2 = -1e30f;
                if (cg + 1 > r1g) s3 = -1e30f;
            }
            sacc[nt][0] = s0; sacc[nt][1] = s1; sacc[nt][2] = s2; sacc[nt][3] = s3;
        }
        float mt0 = -1e30f, mt1 = -1e30f;
#pragma unroll
        for (int nt = 0; nt < 4; nt++) {
            mt0 = fmaxf(mt0, fmaxf(sacc[nt][0], sacc[nt][1]));
            mt1 = fmaxf(mt1, fmaxf(sacc[nt][2], sacc[nt][3]));
        }
        mt0 = fmaxf(mt0, __shfl_xor_sync(0xffffffffu, mt0, 1));
        mt0 = fmaxf(mt0, __shfl_xor_sync(0xffffffffu, mt0, 2));
        mt1 = fmaxf(mt1, __shfl_xor_sync(0xffffffffu, mt1, 1));
        mt1 = fmaxf(mt1, __shfl_xor_sync(0xffffffffu, mt1, 2));

        float ls0 = 0.0f, ls1 = 0.0f;
#pragma unroll
        for (int nt = 0; nt < 4; nt++) {
            float p0 = __expf(sacc[nt][0] - mt0);
            float p1 = __expf(sacc[nt][1] - mt0);
            float p2 = __expf(sacc[nt][2] - mt1);
            float p3 = __expf(sacc[nt][3] - mt1);
            sacc[nt][0] = p0; sacc[nt][1] = p1; sacc[nt][2] = p2; sacc[nt][3] = p3;
            ls0 += p0 + p1; ls1 += p2 + p3;
        }
        ls0 += __shfl_xor_sync(0xffffffffu, ls0, 1);
        ls0 += __shfl_xor_sync(0xffffffffu, ls0, 2);
        ls1 += __shfl_xor_sync(0xffffffffu, ls1, 1);
        ls1 += __shfl_xor_sync(0xffffffffu, ls1, 2);

        __syncthreads();   // (3) all K reads done -> xbuf overlays K region
        if ((l & 3) == 0) {
            *reinterpret_cast<float2*>(smc + S_KH + row0 * 16 + 8 * wj) =
                make_float2(mt0, ls0);
            *reinterpret_cast<float2*>(smc + S_KH + row1 * 16 + 8 * wj) =
                make_float2(mt1, ls1);
        }
        __syncthreads();   // (4) partials visible

        float4 x0 = *reinterpret_cast<const float4*>(smc + S_KH + row0 * 16);
        float4 x1 = *reinterpret_cast<const float4*>(smc + S_KH + row1 * 16);

        float mn0 = fmaxf(m0_, fmaxf(x0.x, x0.z));
        float mn1 = fmaxf(m1_, fmaxf(x1.x, x1.z));
        float al0 = __expf(m0_ - mn0), al1 = __expf(m1_ - mn1);
        float f00 = __expf(x0.x - mn0), f01 = __expf(x0.z - mn0);
        float f10 = __expf(x1.x - mn1), f11 = __expf(x1.z - mn1);
        l0_ = l0_ * al0 + x0.y * f00 + x0.w * f01;
        l1_ = l1_ * al1 + x1.y * f10 + x1.w * f11;
        m0_ = mn0; m1_ = mn1;
        float fme0 = wj ? f01 : f00;
        float fme1 = wj ? f11 : f10;

#pragma unroll
        for (int t = 0; t < 8; t++) {
            O[t][0] *= al0; O[t][1] *= al0; O[t][2] *= al1; O[t][3] *= al1;
        }

        CP_WAIT0();        // V(kt) landed (per-thread)

        // store P hi/lo (swizzled 64x64 bf16 tiles)
#pragma unroll
        for (int nt = 0; nt < 4; nt++) {
            float p00 = sacc[nt][0] * fme0, p01 = sacc[nt][1] * fme0;
            float p10 = sacc[nt][2] * fme1, p11 = sacc[nt][3] * fme1;
            __nv_bfloat16 h00 = __float2bfloat16(p00), h01 = __float2bfloat16(p01);
            __nv_bfloat16 h10 = __float2bfloat16(p10), h11 = __float2bfloat16(p11);
            int unit = 4 * wj + nt;
            unsigned o0 = SWP(row0, unit) + (l & 3) * 4;
            unsigned o1 = SWP(row1, unit) + (l & 3) * 4;
            *reinterpret_cast<unsigned*>(smc + S_PH + o0) = pack2(h00, h01);
            *reinterpret_cast<unsigned*>(smc + S_PH + o1) = pack2(h10, h11);
            *reinterpret_cast<unsigned*>(smc + S_PL + o0) =
                pack2f(p00 - __bfloat162float(h00), p01 - __bfloat162float(h01));
            *reinterpret_cast<unsigned*>(smc + S_PL + o1) =
                pack2f(p10 - __bfloat162float(h10), p11 - __bfloat162float(h11));
        }
        __syncthreads();   // (5) P tiles + V visible to all; xbuf reads done

        // prefetch K(kt+1) under PV compute
        if (kt + 1 < nkt) {
            const int kn = k0 + 64;
#pragma unroll
            for (int t = 0; t < 4; t++) {
                int row = lrow + t * 16;
                size_t g = (size_t)(b * SEQT + kn + row) * HDIM + lq * 8;
                cp16(sb + S_KH + SWB(row, lq), g_Khi + g);
                cp16(sb + S_KL + SWB(row, lq), g_Klo + g);
            }
            CP_COMMIT();
        }

        // ---- O += P V (3-term) ----
#pragma unroll
        for (int ks2 = 0; ks2 < 4; ks2++) {
            unsigned ph[4], pl2[4];
            unsigned p_off = SWP(mi + (l & 15), ks2 * 2 + (l >> 4));
            ldsm4(ph,  sb + S_PH + p_off);
            ldsm4(pl2, sb + S_PL + p_off);
#pragma unroll
            for (int dt2 = 0; dt2 < 4; dt2++) {
                unsigned vh[4], vl[4];
                int vrow = ks2 * 16 + (l & 15);
                unsigned v_off = SWB(vrow, 8 * wj + dt2 * 2 + (l >> 4));
                ldsm4t(vh, sb + S_VH + v_off);
                ldsm4t(vl, sb + S_VL + v_off);
                mma16816(O[2 * dt2],     ph,  vh);
                mma16816(O[2 * dt2 + 1], ph,  vh + 2);
                mma16816(O[2 * dt2],     ph,  vl);
                mma16816(O[2 * dt2 + 1], ph,  vl + 2);
                mma16816(O[2 * dt2],     pl2, vh);
                mma16816(O[2 * dt2 + 1], pl2, vh + 2);
            }
        }
        __syncthreads();   // (1) PV reads done -> V region reusable

        // prefetch V(kt+1) under next iter's QK+softmax
        if (kt + 1 < nkt) {
            const int kn = k0 + 64;
#pragma unroll
            for (int t = 0; t < 4; t++) {
                int row = lrow + t * 16;
                size_t g = (size_t)(b * SEQT + kn + row) * HDIM + lq * 8;
                cp16(sb + S_VH + SWB(row, lq), g_Vhi + g);
                cp16(sb + S_VL + SWB(row, lq), g_Vlo + g);
            }
            CP_COMMIT();
        }
    }

    // epilogue: normalize, store fp32
    float inv0 = 1.0f / l0_, inv1 = 1.0f / l1_;
#pragma unroll
    for (int dt = 0; dt < 8; dt++) {
        int c = 64 * wj + dt * 8 + (l & 3) * 2;
        float2 v0 = make_float2(O[dt][0] * inv0, O[dt][1] * inv0);
        float2 v1 = make_float2(O[dt][2] * inv1, O[dt][3] * inv1);
        *reinterpret_cast<float2*>(out + ((size_t)b * SEQT + r0g) * HDIM + c) = v0;
        *reinterpret_cast<float2*>(out + ((size_t)b * SEQT + r1g) * HDIM + c) = v1;
    }
}

// ---------------------------------------------------------------------------
extern "C" void kernel_launch(void* const* d_in, const int* in_sizes, int n_in,
                              void* d_out, int out_size) {
    const float* x  = (const float*)d_in[0];
    const float* Wq = (const float*)d_in[1];
    const float* bq = (const float*)d_in[2];
    const float* Wk = (const float*)d_in[3];
    const float* bk = (const float*)d_in[4];
    const float* Wv = (const float*)d_in[5];
    const float* bv = (const float*)d_in[6];
    float* out = (float*)d_out;

    split_x_kernel<<<(BT * CDIM / 4) / 256, 256>>>(x);
    split_w_kernel<<<(3 * CDIM * HDIM) / 256, 256>>>(Wq, Wk, Wv);

    cudaFuncSetAttribute(proj_kernel,
                         cudaFuncAttributeMaxDynamicSharedMemorySize, P_SMEM);
    proj_kernel<<<dim3(BT / 128, 1, 3), 256, P_SMEM>>>(bq, bk, bv);

    cudaFuncSetAttribute(attn_kernel,
                         cudaFuncAttributeMaxDynamicSharedMemorySize, A_SMEM);
    attn_kernel<<<dim3(32 * BATCH), 256, A_SMEM>>>(out);
}

// round 8
// speedup vs baseline: 4.6955x; 1.0202x over previous
#include <cuda_runtime.h>
#include <cuda_bf16.h>

#define BATCH 8
#define SEQT 2048
#define CDIM 1024
#define HDIM 128
#define BT (BATCH * SEQT)   // 16384 tokens

// ---------------- device scratch (16B aligned) ----------------
__device__ __align__(16) __nv_bfloat16 g_xhi[BT * CDIM];
__device__ __align__(16) __nv_bfloat16 g_xlo[BT * CDIM];
__device__ __align__(16) __nv_bfloat16 g_whi[3][CDIM * HDIM];  // [c][h]
__device__ __align__(16) __nv_bfloat16 g_wlo[3][CDIM * HDIM];
__device__ __align__(16) __nv_bfloat16 g_Qhi[BT * HDIM];
__device__ __align__(16) __nv_bfloat16 g_Qlo[BT * HDIM];
__device__ __align__(16) __nv_bfloat16 g_Khi[BT * HDIM];
__device__ __align__(16) __nv_bfloat16 g_Vhi[BT * HDIM];
__device__ __align__(16) __nv_bfloat16 g_Vlo[BT * HDIM];

// ---------------- helpers ----------------
__device__ __forceinline__ unsigned smem_u32(const void* p) {
    unsigned a;
    asm("{ .reg .u64 t; cvta.to.shared.u64 t, %1; cvt.u32.u64 %0, t; }"
        : "=r"(a) : "l"(p));
    return a;
}
__device__ __forceinline__ void ldsm4(unsigned* r, unsigned a) {
    asm volatile("ldmatrix.sync.aligned.m8n8.x4.shared.b16 {%0,%1,%2,%3}, [%4];"
                 : "=r"(r[0]), "=r"(r[1]), "=r"(r[2]), "=r"(r[3]) : "r"(a));
}
__device__ __forceinline__ void ldsm4t(unsigned* r, unsigned a) {
    asm volatile("ldmatrix.sync.aligned.m8n8.x4.trans.shared.b16 {%0,%1,%2,%3}, [%4];"
                 : "=r"(r[0]), "=r"(r[1]), "=r"(r[2]), "=r"(r[3]) : "r"(a));
}
__device__ __forceinline__ void mma16816(float* d, const unsigned* a, const unsigned* b) {
    asm volatile(
        "mma.sync.aligned.m16n8k16.row.col.f32.bf16.bf16.f32 "
        "{%0,%1,%2,%3}, {%4,%5,%6,%7}, {%8,%9}, {%0,%1,%2,%3};"
        : "+f"(d[0]), "+f"(d[1]), "+f"(d[2]), "+f"(d[3])
        : "r"(a[0]), "r"(a[1]), "r"(a[2]), "r"(a[3]), "r"(b[0]), "r"(b[1]));
}
__device__ __forceinline__ unsigned pack2(__nv_bfloat16 first, __nv_bfloat16 second) {
    return (unsigned)__bfloat16_as_ushort(first) |
           ((unsigned)__bfloat16_as_ushort(second) << 16);
}
__device__ __forceinline__ unsigned pack2f(float first, float second) {
    return pack2(__float2bfloat16(first), __float2bfloat16(second));
}
__device__ __forceinline__ void cp16(unsigned dst, const void* src) {
    asm volatile("cp.async.cg.shared.global [%0], [%1], 16;"
                 :: "r"(dst), "l"(src));
}
#define CP_COMMIT() asm volatile("cp.async.commit_group;")
#define CP_WAIT0()  asm volatile("cp.async.wait_group 0;" ::: "memory")
#define CP_WAIT1()  asm volatile("cp.async.wait_group 1;" ::: "memory")

// ---------------- prep: split fp32 -> bf16 hi/lo ----------------
__global__ __launch_bounds__(256) void split_x_kernel(const float* __restrict__ x) {
    int i = blockIdx.x * 256 + threadIdx.x;            // float4 index
    float4 v = reinterpret_cast<const float4*>(x)[i];
    __nv_bfloat16 h0 = __float2bfloat16(v.x), h1 = __float2bfloat16(v.y);
    __nv_bfloat16 h2 = __float2bfloat16(v.z), h3 = __float2bfloat16(v.w);
    unsigned* hi = reinterpret_cast<unsigned*>(g_xhi);
    unsigned* lo = reinterpret_cast<unsigned*>(g_xlo);
    hi[2 * i]     = pack2(h0, h1);
    hi[2 * i + 1] = pack2(h2, h3);
    lo[2 * i]     = pack2f(v.x - __bfloat162float(h0), v.y - __bfloat162float(h1));
    lo[2 * i + 1] = pack2f(v.z - __bfloat162float(h2), v.w - __bfloat162float(h3));
}

__global__ __launch_bounds__(256) void split_w_kernel(
    const float* __restrict__ Wq, const float* __restrict__ Wk,
    const float* __restrict__ Wv) {
    int idx = blockIdx.x * 256 + threadIdx.x;          // 0 .. 3*131072-1
    int mat = idx >> 17;
    int r   = idx & 131071;
    const float* W = (mat == 0) ? Wq : (mat == 1) ? Wk : Wv;
    float v = W[r];
    __nv_bfloat16 hi = __float2bfloat16(v);
    g_whi[mat][r] = hi;
    g_wlo[mat][r] = __float2bfloat16(v - __bfloat162float(hi));
}

// ---------------- projection GEMM: 2-stage cp.async pipeline --------------
// Q,K: 2 terms (xhi*Whi + xlo*Whi). V: 3 terms (+ xhi*Wlo).
#define PX_S 72
#define PW_S 136
#define PSTG  71680
#define PP_XH 0
#define PP_XL 18432
#define PP_WH 36864
#define PP_WL 54272
#define P_SMEM (2 * PSTG)   // 143360 B, 1 CTA/SM

__global__ __launch_bounds__(256, 1) void proj_kernel(
    const float* __restrict__ bq, const float* __restrict__ bk,
    const float* __restrict__ bv) {
    extern __shared__ char smc[];
    const unsigned sb = smem_u32(smc);
    const int tid = threadIdx.x;
    const int w   = tid >> 5;
    const int l   = tid & 31;
    const int mat = blockIdx.z;
    const int m0  = blockIdx.x * 128;
    const bool isV = (mat == 2);

    const __nv_bfloat16* Wh = g_whi[mat];
    const __nv_bfloat16* Wl = g_wlo[mat];
    const float* bias = (mat == 0) ? bq : (mat == 1) ? bk : bv;
    __nv_bfloat16* out_hi = (mat == 0) ? g_Qhi : (mat == 1) ? g_Khi : g_Vhi;
    __nv_bfloat16* out_lo = (mat == 0) ? g_Qlo : g_Vlo;   // unused for K

    auto issue_loads = [&](int ch, int s) {
        const int k0 = ch * 64;
        const unsigned st = sb + s * PSTG;
#pragma unroll
        for (int t = 0; t < 4; t++) {
            int u = tid + t * 256;
            int row = u >> 3, q = u & 7;
            unsigned so = (unsigned)((row * PX_S + q * 8) * 2);
            cp16(st + PP_XH + so, g_xhi + (size_t)(m0 + row) * CDIM + k0 + q * 8);
            cp16(st + PP_XL + so, g_xlo + (size_t)(m0 + row) * CDIM + k0 + q * 8);
        }
#pragma unroll
        for (int t = 0; t < 4; t++) {
            int u = tid + t * 256;
            int row = u >> 4, q = u & 15;
            unsigned so = (unsigned)((row * PW_S + q * 8) * 2);
            cp16(st + PP_WH + so, Wh + (size_t)(k0 + row) * HDIM + q * 8);
            if (isV)
                cp16(st + PP_WL + so, Wl + (size_t)(k0 + row) * HDIM + q * 8);
        }
        CP_COMMIT();
    };

    float acc[16][4];
#pragma unroll
    for (int t = 0; t < 16; t++)
#pragma unroll
        for (int r = 0; r < 4; r++) acc[t][r] = 0.0f;

    issue_loads(0, 0);

    for (int ch = 0; ch < 16; ch++) {
        const int s = ch & 1;
        if (ch < 15) {
            issue_loads(ch + 1, s ^ 1);
            CP_WAIT1();
        } else {
            CP_WAIT0();
        }
        __syncthreads();   // stage s visible

        const unsigned st = sb + s * PSTG;
#pragma unroll
        for (int ks = 0; ks < 4; ks++) {
            const int kk = ks * 16;
            unsigned ah[4], al[4];
            unsigned a_addr = st + PP_XH +
                ((w * 16 + (l & 15)) * PX_S + kk + 8 * (l >> 4)) * 2;
            ldsm4(ah, a_addr);
            ldsm4(al, a_addr + (PP_XL - PP_XH));
#pragma unroll
            for (int nt2 = 0; nt2 < 8; nt2++) {
                unsigned bh[4];
                unsigned b_addr = st + PP_WH +
                    ((kk + (l & 15)) * PW_S + nt2 * 16 + 8 * (l >> 4)) * 2;
                ldsm4t(bh, b_addr);
                mma16816(acc[2 * nt2],     ah, bh);
                mma16816(acc[2 * nt2 + 1], ah, bh + 2);
                mma16816(acc[2 * nt2],     al, bh);
                mma16816(acc[2 * nt2 + 1], al, bh + 2);
                if (isV) {
                    unsigned bl[4];
                    ldsm4t(bl, b_addr + (PP_WL - PP_WH));
                    mma16816(acc[2 * nt2],     ah, bl);
                    mma16816(acc[2 * nt2 + 1], ah, bl + 2);
                }
            }
        }
        __syncthreads();   // stage s consumed before overwrite
    }

    const int r0 = m0 + w * 16 + (l >> 2);
    const int r1 = r0 + 8;
#pragma unroll
    for (int nt = 0; nt < 16; nt++) {
        int c = nt * 8 + (l & 3) * 2;
        float vals[4] = {acc[nt][0] + bias[c], acc[nt][1] + bias[c + 1],
                         acc[nt][2] + bias[c], acc[nt][3] + bias[c + 1]};
        int rows[4] = {r0, r0, r1, r1};
        int cols[4] = {c, c + 1, c, c + 1};
#pragma unroll
        for (int e = 0; e < 4; e++) {
            size_t off = (size_t)rows[e] * HDIM + cols[e];
            __nv_bfloat16 h = __float2bfloat16(vals[e]);
            out_hi[off] = h;
            if (mat != 1)   // K needs no lo (QK uses Khi only)
                out_lo[off] = __float2bfloat16(vals[e] - __bfloat162float(h));
        }
    }
}

// ---------------- flash attention: BQ=64, 8 warps, 2 CTAs/SM --------------
// QK 2-term (Qhi*Khi + Qlo*Khi), PV 3-term. 4 barriers/iter, dedicated xbuf.
#define S_QH 0
#define S_QL 16384
#define S_KH 32768
#define S_VH 49152
#define S_VL 65536
#define S_PH 81920
#define S_PL 90112
#define S_XB 98304
#define A_SMEM 99328
#define SWB(row, unit) (((row) << 8) + ((((unit) ^ ((row) & 7))) << 4))
#define SWP(row, unit) (((row) << 7) + ((((unit) ^ ((row) & 7))) << 4))

__global__ __launch_bounds__(256, 2) void attn_kernel(float* __restrict__ out) {
    extern __shared__ char smc[];
    const unsigned sb = smem_u32(smc);
    const int tid = threadIdx.x;
    const int w   = tid >> 5;          // 0..7
    const int l   = tid & 31;
    const int wi  = w >> 1;            // m-block 0..3
    const int wj  = w & 1;             // n-half 0..1
    const int mi  = wi * 16;
    const int qt  = 31 - (blockIdx.x >> 3);   // heavy tiles first
    const int b   = blockIdx.x & 7;
    const int q0  = qt * 64;
    const float scale = 0.03125f;      // 1024^-0.5

    const int lrow = (tid >> 4);
    const int lq   = tid & 15;

    // prologue: group0 = Q(hi,lo) + K(0); group1 = V(0)
#pragma unroll
    for (int t = 0; t < 4; t++) {
        int row = lrow + t * 16;
        size_t g = (size_t)(b * SEQT + q0 + row) * HDIM + lq * 8;
        cp16(sb + S_QH + SWB(row, lq), g_Qhi + g);
        cp16(sb + S_QL + SWB(row, lq), g_Qlo + g);
    }
#pragma unroll
    for (int t = 0; t < 4; t++) {
        int row = lrow + t * 16;
        size_t g = (size_t)(b * SEQT + row) * HDIM + lq * 8;
        cp16(sb + S_KH + SWB(row, lq), g_Khi + g);
    }
    CP_COMMIT();
#pragma unroll
    for (int t = 0; t < 4; t++) {
        int row = lrow + t * 16;
        size_t g = (size_t)(b * SEQT + row) * HDIM + lq * 8;
        cp16(sb + S_VH + SWB(row, lq), g_Vhi + g);
        cp16(sb + S_VL + SWB(row, lq), g_Vlo + g);
    }
    CP_COMMIT();

    float m0_ = -1e30f, m1_ = -1e30f, l0_ = 0.0f, l1_ = 0.0f;
    float O[8][4];
#pragma unroll
    for (int t = 0; t < 8; t++)
#pragma unroll
        for (int r = 0; r < 4; r++) O[t][r] = 0.0f;

    const int row0 = mi + (l >> 2);
    const int row1 = row0 + 8;
    const int r0g  = q0 + row0;
    const int r1g  = r0g + 8;
    const int nkt  = qt + 1;

    for (int kt = 0; kt < nkt; kt++) {
        const int k0 = kt * 64;
        CP_WAIT1();        // K(kt) (and Q) landed; V(kt) may still fly
        __syncthreads();   // (A) K visible cross-thread

        // ---- S = Q K^T (2-term) ----
        float sacc[4][4];
#pragma unroll
        for (int t = 0; t < 4; t++)
#pragma unroll
            for (int r = 0; r < 4; r++) sacc[t][r] = 0.0f;

#pragma unroll
        for (int ks = 0; ks < 8; ks++) {
            unsigned ah[4], al[4];
            unsigned a_off = SWB(mi + (l & 15), ks * 2 + (l >> 4));
            ldsm4(ah, sb + S_QH + a_off);
            ldsm4(al, sb + S_QL + a_off);
#pragma unroll
            for (int nt2 = 0; nt2 < 2; nt2++) {
                unsigned bh[4];
                int brow = 32 * wj + nt2 * 16 + ((l >> 4) << 3) + (l & 7);
                unsigned b_off = SWB(brow, ks * 2 + ((l >> 3) & 1));
                ldsm4(bh, sb + S_KH + b_off);
                mma16816(sacc[2 * nt2],     ah, bh);
                mma16816(sacc[2 * nt2 + 1], ah, bh + 2);
                mma16816(sacc[2 * nt2],     al, bh);
                mma16816(sacc[2 * nt2 + 1], al, bh + 2);
            }
        }

        // ---- local softmax (this warp's 32 cols) ----
        const bool mask_it = (kt == qt);
#pragma unroll
        for (int nt = 0; nt < 4; nt++) {
            int cg = k0 + 32 * wj + nt * 8 + (l & 3) * 2;
            float s0 = sacc[nt][0] * scale, s1 = sacc[nt][1] * scale;
            float s2 = sacc[nt][2] * scale, s3 = sacc[nt][3] * scale;
            if (mask_it) {
                if (cg     > r0g) s0 = -1e30f;
                if (cg + 1 > r0g) s1 = -1e30f;
                if (cg     > r1g) s2 = -1e30f;
                if (cg + 1 > r1g) s3 = -1e30f;
            }
            sacc[nt][0] = s0; sacc[nt][1] = s1; sacc[nt][2] = s2; sacc[nt][3] = s3;
        }
        float mt0 = -1e30f, mt1 = -1e30f;
#pragma unroll
        for (int nt = 0; nt < 4; nt++) {
            mt0 = fmaxf(mt0, fmaxf(sacc[nt][0], sacc[nt][1]));
            mt1 = fmaxf(mt1, fmaxf(sacc[nt][2], sacc[nt][3]));
        }
        mt0 = fmaxf(mt0, __shfl_xor_sync(0xffffffffu, mt0, 1));
        mt0 = fmaxf(mt0, __shfl_xor_sync(0xffffffffu, mt0, 2));
        mt1 = fmaxf(mt1, __shfl_xor_sync(0xffffffffu, mt1, 1));
        mt1 = fmaxf(mt1, __shfl_xor_sync(0xffffffffu, mt1, 2));

        float ls0 = 0.0f, ls1 = 0.0f;
#pragma unroll
        for (int nt = 0; nt < 4; nt++) {
            float p0 = __expf(sacc[nt][0] - mt0);
            float p1 = __expf(sacc[nt][1] - mt0);
            float p2 = __expf(sacc[nt][2] - mt1);
            float p3 = __expf(sacc[nt][3] - mt1);
            sacc[nt][0] = p0; sacc[nt][1] = p1; sacc[nt][2] = p2; sacc[nt][3] = p3;
            ls0 += p0 + p1; ls1 += p2 + p3;
        }
        ls0 += __shfl_xor_sync(0xffffffffu, ls0, 1);
        ls0 += __shfl_xor_sync(0xffffffffu, ls0, 2);
        ls1 += __shfl_xor_sync(0xffffffffu, ls1, 1);
        ls1 += __shfl_xor_sync(0xffffffffu, ls1, 2);

        // cross-warp softmax exchange via dedicated xbuf
        if ((l & 3) == 0) {
            *reinterpret_cast<float2*>(smc + S_XB + row0 * 16 + 8 * wj) =
                make_float2(mt0, ls0);
            *reinterpret_cast<float2*>(smc + S_XB + row1 * 16 + 8 * wj) =
                make_float2(mt1, ls1);
        }
        __syncthreads();   // (B) partials visible

        float4 x0 = *reinterpret_cast<const float4*>(smc + S_XB + row0 * 16);
        float4 x1 = *reinterpret_cast<const float4*>(smc + S_XB + row1 * 16);

        float mn0 = fmaxf(m0_, fmaxf(x0.x, x0.z));
        float mn1 = fmaxf(m1_, fmaxf(x1.x, x1.z));
        float al0 = __expf(m0_ - mn0), al1 = __expf(m1_ - mn1);
        float f00 = __expf(x0.x - mn0), f01 = __expf(x0.z - mn0);
        float f10 = __expf(x1.x - mn1), f11 = __expf(x1.z - mn1);
        l0_ = l0_ * al0 + x0.y * f00 + x0.w * f01;
        l1_ = l1_ * al1 + x1.y * f10 + x1.w * f11;
        m0_ = mn0; m1_ = mn1;
        float fme0 = wj ? f01 : f00;
        float fme1 = wj ? f11 : f10;

#pragma unroll
        for (int t = 0; t < 8; t++) {
            O[t][0] *= al0; O[t][1] *= al0; O[t][2] *= al1; O[t][3] *= al1;
        }

        CP_WAIT0();        // V(kt) landed (per-thread)

        // store P hi/lo (swizzled 64x64 bf16 tiles)
#pragma unroll
        for (int nt = 0; nt < 4; nt++) {
            float p00 = sacc[nt][0] * fme0, p01 = sacc[nt][1] * fme0;
            float p10 = sacc[nt][2] * fme1, p11 = sacc[nt][3] * fme1;
            __nv_bfloat16 h00 = __float2bfloat16(p00), h01 = __float2bfloat16(p01);
            __nv_bfloat16 h10 = __float2bfloat16(p10), h11 = __float2bfloat16(p11);
            int unit = 4 * wj + nt;
            unsigned o0 = SWP(row0, unit) + (l & 3) * 4;
            unsigned o1 = SWP(row1, unit) + (l & 3) * 4;
            *reinterpret_cast<unsigned*>(smc + S_PH + o0) = pack2(h00, h01);
            *reinterpret_cast<unsigned*>(smc + S_PH + o1) = pack2(h10, h11);
            *reinterpret_cast<unsigned*>(smc + S_PL + o0) =
                pack2f(p00 - __bfloat162float(h00), p01 - __bfloat162float(h01));
            *reinterpret_cast<unsigned*>(smc + S_PL + o1) =
                pack2f(p10 - __bfloat162float(h10), p11 - __bfloat162float(h11));
        }
        __syncthreads();   // (C) P + V visible; K/xbuf reads all done

        // prefetch K(kt+1) under PV compute
        if (kt + 1 < nkt) {
            const int kn = k0 + 64;
#pragma unroll
            for (int t = 0; t < 4; t++) {
                int row = lrow + t * 16;
                size_t g = (size_t)(b * SEQT + kn + row) * HDIM + lq * 8;
                cp16(sb + S_KH + SWB(row, lq), g_Khi + g);
            }
            CP_COMMIT();
        }

        // ---- O += P V (3-term) ----
#pragma unroll
        for (int ks2 = 0; ks2 < 4; ks2++) {
            unsigned ph[4], pl2[4];
            unsigned p_off = SWP(mi + (l & 15), ks2 * 2 + (l >> 4));
            ldsm4(ph,  sb + S_PH + p_off);
            ldsm4(pl2, sb + S_PL + p_off);
#pragma unroll
            for (int dt2 = 0; dt2 < 4; dt2++) {
                unsigned vh[4], vl[4];
                int vrow = ks2 * 16 + (l & 15);
                unsigned v_off = SWB(vrow, 8 * wj + dt2 * 2 + (l >> 4));
                ldsm4t(vh, sb + S_VH + v_off);
                ldsm4t(vl, sb + S_VL + v_off);
                mma16816(O[2 * dt2],     ph,  vh);
                mma16816(O[2 * dt2 + 1], ph,  vh + 2);
                mma16816(O[2 * dt2],     ph,  vl);
                mma16816(O[2 * dt2 + 1], ph,  vl + 2);
                mma16816(O[2 * dt2],     pl2, vh);
                mma16816(O[2 * dt2 + 1], pl2, vh + 2);
            }
        }
        __syncthreads();   // (D) PV reads done -> V region reusable

        // prefetch V(kt+1) under next iter's QK+softmax
        if (kt + 1 < nkt) {
            const int kn = k0 + 64;
#pragma unroll
            for (int t = 0; t < 4; t++) {
                int row = lrow + t * 16;
                size_t g = (size_t)(b * SEQT + kn + row) * HDIM + lq * 8;
                cp16(sb + S_VH + SWB(row, lq), g_Vhi + g);
                cp16(sb + S_VL + SWB(row, lq), g_Vlo + g);
            }
            CP_COMMIT();
        }
    }

    // epilogue: normalize, store fp32
    float inv0 = 1.0f / l0_, inv1 = 1.0f / l1_;
#pragma unroll
    for (int dt = 0; dt < 8; dt++) {
        int c = 64 * wj + dt * 8 + (l & 3) * 2;
        float2 v0 = make_float2(O[dt][0] * inv0, O[dt][1] * inv0);
        float2 v1 = make_float2(O[dt][2] * inv1, O[dt][3] * inv1);
        *reinterpret_cast<float2*>(out + ((size_t)b * SEQT + r0g) * HDIM + c) = v0;
        *reinterpret_cast<float2*>(out + ((size_t)b * SEQT + r1g) * HDIM + c) = v1;
    }
}

// ---------------------------------------------------------------------------
extern "C" void kernel_launch(void* const* d_in, const int* in_sizes, int n_in,
                              void* d_out, int out_size) {
    const float* x  = (const float*)d_in[0];
    const float* Wq = (const float*)d_in[1];
    const float* bq = (const float*)d_in[2];
    const float* Wk = (const float*)d_in[3];
    const float* bk = (const float*)d_in[4];
    const float* Wv = (const float*)d_in[5];
    const float* bv = (const float*)d_in[6];
    float* out = (float*)d_out;

    split_x_kernel<<<(BT * CDIM / 4) / 256, 256>>>(x);
    split_w_kernel<<<(3 * CDIM * HDIM) / 256, 256>>>(Wq, Wk, Wv);

    cudaFuncSetAttribute(proj_kernel,
                         cudaFuncAttributeMaxDynamicSharedMemorySize, P_SMEM);
    proj_kernel<<<dim3(BT / 128, 1, 3), 256, P_SMEM>>>(bq, bk, bv);

    cudaFuncSetAttribute(attn_kernel,
                         cudaFuncAttributeMaxDynamicSharedMemorySize, A_SMEM);
    attn_kernel<<<dim3(32 * BATCH), 256, A_SMEM>>>(out);
}

// round 9
// speedup vs baseline: 6.1053x; 1.3002x over previous
#include <cuda_runtime.h>
#include <cuda_bf16.h>

#define BATCH 8
#define SEQT 2048
#define CDIM 1024
#define HDIM 128
#define BT (BATCH * SEQT)   // 16384 tokens

// ---------------- device scratch (16B aligned) ----------------
__device__ __align__(16) __nv_bfloat16 g_whi[3][CDIM * HDIM];  // [c][h]
__device__ __align__(16) __nv_bfloat16 g_wlo[3][CDIM * HDIM];
__device__ __align__(16) __nv_bfloat16 g_Qhi[BT * HDIM];
__device__ __align__(16) __nv_bfloat16 g_Qlo[BT * HDIM];
__device__ __align__(16) __nv_bfloat16 g_Khi[BT * HDIM];
__device__ __align__(16) __nv_bfloat16 g_Vhi[BT * HDIM];
__device__ __align__(16) __nv_bfloat16 g_Vlo[BT * HDIM];

// ---------------- helpers ----------------
__device__ __forceinline__ unsigned smem_u32(const void* p) {
    unsigned a;
    asm("{ .reg .u64 t; cvta.to.shared.u64 t, %1; cvt.u32.u64 %0, t; }"
        : "=r"(a) : "l"(p));
    return a;
}
__device__ __forceinline__ void ldsm4(unsigned* r, unsigned a) {
    asm volatile("ldmatrix.sync.aligned.m8n8.x4.shared.b16 {%0,%1,%2,%3}, [%4];"
                 : "=r"(r[0]), "=r"(r[1]), "=r"(r[2]), "=r"(r[3]) : "r"(a));
}
__device__ __forceinline__ void ldsm4t(unsigned* r, unsigned a) {
    asm volatile("ldmatrix.sync.aligned.m8n8.x4.trans.shared.b16 {%0,%1,%2,%3}, [%4];"
                 : "=r"(r[0]), "=r"(r[1]), "=r"(r[2]), "=r"(r[3]) : "r"(a));
}
__device__ __forceinline__ void mma16816(float* d, const unsigned* a, const unsigned* b) {
    asm volatile(
        "mma.sync.aligned.m16n8k16.row.col.f32.bf16.bf16.f32 "
        "{%0,%1,%2,%3}, {%4,%5,%6,%7}, {%8,%9}, {%0,%1,%2,%3};"
        : "+f"(d[0]), "+f"(d[1]), "+f"(d[2]), "+f"(d[3])
        : "r"(a[0]), "r"(a[1]), "r"(a[2]), "r"(a[3]), "r"(b[0]), "r"(b[1]));
}
__device__ __forceinline__ unsigned pack2(__nv_bfloat16 first, __nv_bfloat16 second) {
    return (unsigned)__bfloat16_as_ushort(first) |
           ((unsigned)__bfloat16_as_ushort(second) << 16);
}
__device__ __forceinline__ unsigned pack2f(float first, float second) {
    return pack2(__float2bfloat16(first), __float2bfloat16(second));
}
__device__ __forceinline__ void cp16(unsigned dst, const void* src) {
    asm volatile("cp.async.cg.shared.global [%0], [%1], 16;"
                 :: "r"(dst), "l"(src));
}
#define CP_COMMIT() asm volatile("cp.async.commit_group;")
#define CP_WAIT0()  asm volatile("cp.async.wait_group 0;" ::: "memory")
#define CP_WAIT1()  asm volatile("cp.async.wait_group 1;" ::: "memory")

// ---------------- prep: split W fp32 -> bf16 hi/lo ----------------
__global__ __launch_bounds__(256) void split_w_kernel(
    const float* __restrict__ Wq, const float* __restrict__ Wk,
    const float* __restrict__ Wv) {
    int idx = blockIdx.x * 256 + threadIdx.x;          // 0 .. 3*131072-1
    int mat = idx >> 17;
    int r   = idx & 131071;
    const float* W = (mat == 0) ? Wq : (mat == 1) ? Wk : Wv;
    float v = W[r];
    __nv_bfloat16 hi = __float2bfloat16(v);
    g_whi[mat][r] = hi;
    g_wlo[mat][r] = __float2bfloat16(v - __bfloat162float(hi));
}

// ---------------- fused QKV projection ----------------
// M=32 tokens/CTA, grid 512, 256 thr (8 warps = 2m x 4n), 2 CTAs/SM.
// K chunks of 32 (32 chunks). x fp32 loaded + split to bf16 hi/lo in-kernel.
// Q,K: 2 terms (xh*Wh + xl*Wh). V: 3 terms (+ xh*Wl).
#define FM 32
#define FK 32
#define F_XF(s)    ((s) * 4096)                         // 32 x 128B fp32
#define F_W(s, m)  (8192 + (s) * 32768 + (m) * 8192)    // 32 x 256B bf16
#define F_XH 73728                                      // 32 rows stride 80B
#define F_XL 76288
#define F_SMEM 78848
#define SWB(row, unit) (((row) << 8) + ((((unit) ^ ((row) & 7))) << 4))

__global__ __launch_bounds__(256, 2) void fused_proj_kernel(
    const float* __restrict__ x,
    const float* __restrict__ bq, const float* __restrict__ bk,
    const float* __restrict__ bv) {
    extern __shared__ char smc[];
    const unsigned sb = smem_u32(smc);
    const int tid = threadIdx.x;
    const int w   = tid >> 5;
    const int l   = tid & 31;
    const int wi  = w >> 2;            // m-block 0..1
    const int wj  = w & 3;             // n-quarter 0..3
    const int mi  = wi * 16;
    const int m0  = blockIdx.x * FM;

    const __nv_bfloat16* wsrc[4] = {g_whi[0], g_whi[1], g_whi[2], g_wlo[2]};

    // load mappings
    const int xrow = tid >> 3, xq = tid & 7;     // x fp32: 1 cp16/thread

    auto issue_loads = [&](int ch, int s) {
        const int k0 = ch * FK;
        // x fp32 tile: 32 rows x 32 fp32
        cp16(sb + F_XF(s) + xrow * 128 + xq * 16,
             x + (size_t)(m0 + xrow) * CDIM + k0 + xq * 4);
        // W tiles: 4 x (32 rows x 128 bf16)
#pragma unroll
        for (int t = 0; t < 8; t++) {
            int u = tid + t * 256;                // 0..2047
            int m = u >> 9;
            int r = (u >> 4) & 31;
            int q = u & 15;
            cp16(sb + F_W(s, m) + SWB(r, q),
                 wsrc[m] + (size_t)(k0 + r) * HDIM + q * 8);
        }
        CP_COMMIT();
    };

    float acc[3][4][4];
#pragma unroll
    for (int m = 0; m < 3; m++)
#pragma unroll
        for (int t = 0; t < 4; t++)
#pragma unroll
            for (int r = 0; r < 4; r++) acc[m][t][r] = 0.0f;

    issue_loads(0, 0);

    for (int ch = 0; ch < 32; ch++) {
        const int s = ch & 1;
        CP_WAIT0();        // group(ch) landed (only one outstanding here)
        __syncthreads();   // barA: stage s visible; MMA(ch-1) done everywhere

        if (ch + 1 < 32) issue_loads(ch + 1, s ^ 1);

        // convert x fp32 -> bf16 hi/lo (each thread: 1 float4)
        {
            float4 v = *reinterpret_cast<const float4*>(
                smc + F_XF(s) + xrow * 128 + xq * 16);
            __nv_bfloat16 h0 = __float2bfloat16(v.x), h1 = __float2bfloat16(v.y);
            __nv_bfloat16 h2 = __float2bfloat16(v.z), h3 = __float2bfloat16(v.w);
            uint2 hv, lv;
            hv.x = pack2(h0, h1);
            hv.y = pack2(h2, h3);
            lv.x = pack2f(v.x - __bfloat162float(h0), v.y - __bfloat162float(h1));
            lv.y = pack2f(v.z - __bfloat162float(h2), v.w - __bfloat162float(h3));
            *reinterpret_cast<uint2*>(smc + F_XH + xrow * 80 + xq * 8) = hv;
            *reinterpret_cast<uint2*>(smc + F_XL + xrow * 80 + xq * 8) = lv;
        }
        __syncthreads();   // barB: conversion visible

        // MMA: A frags reused across 4 weight matrices
#pragma unroll
        for (int ks = 0; ks < 2; ks++) {
            unsigned ah[4], al[4];
            unsigned a_off = (mi + (l & 15)) * 80 + (ks * 2 + (l >> 4)) * 16;
            ldsm4(ah, sb + F_XH + a_off);
            ldsm4(al, sb + F_XL + a_off);
            const int brow = ks * 16 + (l & 15);
#pragma unroll
            for (int m = 0; m < 3; m++) {
#pragma unroll
                for (int nt2 = 0; nt2 < 2; nt2++) {
                    unsigned bh[4];
                    unsigned unit = wj * 4 + nt2 * 2 + (l >> 4);
                    ldsm4t(bh, sb + F_W(s, m) + SWB(brow, unit));
                    mma16816(acc[m][2 * nt2],     ah, bh);
                    mma16816(acc[m][2 * nt2 + 1], ah, bh + 2);
                    mma16816(acc[m][2 * nt2],     al, bh);
                    mma16816(acc[m][2 * nt2 + 1], al, bh + 2);
                }
            }
            // V lo term (xh * Wvlo)
#pragma unroll
            for (int nt2 = 0; nt2 < 2; nt2++) {
                unsigned bl[4];
                unsigned unit = wj * 4 + nt2 * 2 + (l >> 4);
                ldsm4t(bl, sb + F_W(s, 3) + SWB(brow, unit));
                mma16816(acc[2][2 * nt2],     ah, bl);
                mma16816(acc[2][2 * nt2 + 1], ah, bl + 2);
            }
        }
    }

    // epilogue
    const int r0 = m0 + mi + (l >> 2);
    const int r1 = r0 + 8;
    const float* biases[3] = {bq, bk, bv};
#pragma unroll
    for (int m = 0; m < 3; m++) {
        __nv_bfloat16* ohi = (m == 0) ? g_Qhi : (m == 1) ? g_Khi : g_Vhi;
        __nv_bfloat16* olo = (m == 0) ? g_Qlo : g_Vlo;   // unused for K
#pragma unroll
        for (int nt = 0; nt < 4; nt++) {
            int c = wj * 32 + nt * 8 + (l & 3) * 2;
            float b0 = biases[m][c], b1 = biases[m][c + 1];
            float vals[4] = {acc[m][nt][0] + b0, acc[m][nt][1] + b1,
                             acc[m][nt][2] + b0, acc[m][nt][3] + b1};
            int rows[4] = {r0, r0, r1, r1};
            int cols[4] = {c, c + 1, c, c + 1};
#pragma unroll
            for (int e = 0; e < 4; e++) {
                size_t off = (size_t)rows[e] * HDIM + cols[e];
                __nv_bfloat16 h = __float2bfloat16(vals[e]);
                ohi[off] = h;
                if (m != 1)
                    olo[off] = __float2bfloat16(vals[e] - __bfloat162float(h));
            }
        }
    }
}

// ---------------- flash attention (unchanged from R8) ---------------------
#define S_QH 0
#define S_QL 16384
#define S_KH 32768
#define S_VH 49152
#define S_VL 65536
#define S_PH 81920
#define S_PL 90112
#define S_XB 98304
#define A_SMEM 99328
#define SWP(row, unit) (((row) << 7) + ((((unit) ^ ((row) & 7))) << 4))

__global__ __launch_bounds__(256, 2) void attn_kernel(float* __restrict__ out) {
    extern __shared__ char smc[];
    const unsigned sb = smem_u32(smc);
    const int tid = threadIdx.x;
    const int w   = tid >> 5;          // 0..7
    const int l   = tid & 31;
    const int wi  = w >> 1;            // m-block 0..3
    const int wj  = w & 1;             // n-half 0..1
    const int mi  = wi * 16;
    const int qt  = 31 - (blockIdx.x >> 3);   // heavy tiles first
    const int b   = blockIdx.x & 7;
    const int q0  = qt * 64;
    const float scale = 0.03125f;      // 1024^-0.5

    const int lrow = (tid >> 4);
    const int lq   = tid & 15;

    // prologue: group0 = Q(hi,lo) + K(0); group1 = V(0)
#pragma unroll
    for (int t = 0; t < 4; t++) {
        int row = lrow + t * 16;
        size_t g = (size_t)(b * SEQT + q0 + row) * HDIM + lq * 8;
        cp16(sb + S_QH + SWB(row, lq), g_Qhi + g);
        cp16(sb + S_QL + SWB(row, lq), g_Qlo + g);
    }
#pragma unroll
    for (int t = 0; t < 4; t++) {
        int row = lrow + t * 16;
        size_t g = (size_t)(b * SEQT + row) * HDIM + lq * 8;
        cp16(sb + S_KH + SWB(row, lq), g_Khi + g);
    }
    CP_COMMIT();
#pragma unroll
    for (int t = 0; t < 4; t++) {
        int row = lrow + t * 16;
        size_t g = (size_t)(b * SEQT + row) * HDIM + lq * 8;
        cp16(sb + S_VH + SWB(row, lq), g_Vhi + g);
        cp16(sb + S_VL + SWB(row, lq), g_Vlo + g);
    }
    CP_COMMIT();

    float m0_ = -1e30f, m1_ = -1e30f, l0_ = 0.0f, l1_ = 0.0f;
    float O[8][4];
#pragma unroll
    for (int t = 0; t < 8; t++)
#pragma unroll
        for (int r = 0; r < 4; r++) O[t][r] = 0.0f;

    const int row0 = mi + (l >> 2);
    const int row1 = row0 + 8;
    const int r0g  = q0 + row0;
    const int r1g  = r0g + 8;
    const int nkt  = qt + 1;

    for (int kt = 0; kt < nkt; kt++) {
        const int k0 = kt * 64;
        CP_WAIT1();
        __syncthreads();   // (A) K visible

        float sacc[4][4];
#pragma unroll
        for (int t = 0; t < 4; t++)
#pragma unroll
            for (int r = 0; r < 4; r++) sacc[t][r] = 0.0f;

#pragma unroll
        for (int ks = 0; ks < 8; ks++) {
            unsigned ah[4], al[4];
            unsigned a_off = SWB(mi + (l & 15), ks * 2 + (l >> 4));
            ldsm4(ah, sb + S_QH + a_off);
            ldsm4(al, sb + S_QL + a_off);
#pragma unroll
            for (int nt2 = 0; nt2 < 2; nt2++) {
                unsigned bh[4];
                int brow = 32 * wj + nt2 * 16 + ((l >> 4) << 3) + (l & 7);
                unsigned b_off = SWB(brow, ks * 2 + ((l >> 3) & 1));
                ldsm4(bh, sb + S_KH + b_off);
                mma16816(sacc[2 * nt2],     ah, bh);
                mma16816(sacc[2 * nt2 + 1], ah, bh + 2);
                mma16816(sacc[2 * nt2],     al, bh);
                mma16816(sacc[2 * nt2 + 1], al, bh + 2);
            }
        }

        const bool mask_it = (kt == qt);
#pragma unroll
        for (int nt = 0; nt < 4; nt++) {
            int cg = k0 + 32 * wj + nt * 8 + (l & 3) * 2;
            float s0 = sacc[nt][0] * scale, s1 = sacc[nt][1] * scale;
            float s2 = sacc[nt][2] * scale, s3 = sacc[nt][3] * scale;
            if (mask_it) {
                if (cg     > r0g) s0 = -1e30f;
                if (cg + 1 > r0g) s1 = -1e30f;
                if (cg     > r1g) s2 = -1e30f;
                if (cg + 1 > r1g) s3 = -1e30f;
            }
            sacc[nt][0] = s0; sacc[nt][1] = s1; sacc[nt][2] = s2; sacc[nt][3] = s3;
        }
        float mt0 = -1e30f, mt1 = -1e30f;
#pragma unroll
        for (int nt = 0; nt < 4; nt++) {
            mt0 = fmaxf(mt0, fmaxf(sacc[nt][0], sacc[nt][1]));
            mt1 = fmaxf(mt1, fmaxf(sacc[nt][2], sacc[nt][3]));
        }
        mt0 = fmaxf(mt0, __shfl_xor_sync(0xffffffffu, mt0, 1));
        mt0 = fmaxf(mt0, __shfl_xor_sync(0xffffffffu, mt0, 2));
        mt1 = fmaxf(mt1, __shfl_xor_sync(0xffffffffu, mt1, 1));
        mt1 = fmaxf(mt1, __shfl_xor_sync(0xffffffffu, mt1, 2));

        float ls0 = 0.0f, ls1 = 0.0f;
#pragma unroll
        for (int nt = 0; nt < 4; nt++) {
            float p0 = __expf(sacc[nt][0] - mt0);
            float p1 = __expf(sacc[nt][1] - mt0);
            float p2 = __expf(sacc[nt][2] - mt1);
            float p3 = __expf(sacc[nt][3] - mt1);
            sacc[nt][0] = p0; sacc[nt][1] = p1; sacc[nt][2] = p2; sacc[nt][3] = p3;
            ls0 += p0 + p1; ls1 += p2 + p3;
        }
        ls0 += __shfl_xor_sync(0xffffffffu, ls0, 1);
        ls0 += __shfl_xor_sync(0xffffffffu, ls0, 2);
        ls1 += __shfl_xor_sync(0xffffffffu, ls1, 1);
        ls1 += __shfl_xor_sync(0xffffffffu, ls1, 2);

        if ((l & 3) == 0) {
            *reinterpret_cast<float2*>(smc + S_XB + row0 * 16 + 8 * wj) =
                make_float2(mt0, ls0);
            *reinterpret_cast<float2*>(smc + S_XB + row1 * 16 + 8 * wj) =
                make_float2(mt1, ls1);
        }
        __syncthreads();   // (B) partials visible

        float4 x0 = *reinterpret_cast<const float4*>(smc + S_XB + row0 * 16);
        float4 x1 = *reinterpret_cast<const float4*>(smc + S_XB + row1 * 16);

        float mn0 = fmaxf(m0_, fmaxf(x0.x, x0.z));
        float mn1 = fmaxf(m1_, fmaxf(x1.x, x1.z));
        float al0 = __expf(m0_ - mn0), al1 = __expf(m1_ - mn1);
        float f00 = __expf(x0.x - mn0), f01 = __expf(x0.z - mn0);
        float f10 = __expf(x1.x - mn1), f11 = __expf(x1.z - mn1);
        l0_ = l0_ * al0 + x0.y * f00 + x0.w * f01;
        l1_ = l1_ * al1 + x1.y * f10 + x1.w * f11;
        m0_ = mn0; m1_ = mn1;
        float fme0 = wj ? f01 : f00;
        float fme1 = wj ? f11 : f10;

#pragma unroll
        for (int t = 0; t < 8; t++) {
            O[t][0] *= al0; O[t][1] *= al0; O[t][2] *= al1; O[t][3] *= al1;
        }

        CP_WAIT0();        // V(kt) landed

#pragma unroll
        for (int nt = 0; nt < 4; nt++) {
            float p00 = sacc[nt][0] * fme0, p01 = sacc[nt][1] * fme0;
            float p10 = sacc[nt][2] * fme1, p11 = sacc[nt][3] * fme1;
            __nv_bfloat16 h00 = __float2bfloat16(p00), h01 = __float2bfloat16(p01);
            __nv_bfloat16 h10 = __float2bfloat16(p10), h11 = __float2bfloat16(p11);
            int unit = 4 * wj + nt;
            unsigned o0 = SWP(row0, unit) + (l & 3) * 4;
            unsigned o1 = SWP(row1, unit) + (l & 3) * 4;
            *reinterpret_cast<unsigned*>(smc + S_PH + o0) = pack2(h00, h01);
            *reinterpret_cast<unsigned*>(smc + S_PH + o1) = pack2(h10, h11);
            *reinterpret_cast<unsigned*>(smc + S_PL + o0) =
                pack2f(p00 - __bfloat162float(h00), p01 - __bfloat162float(h01));
            *reinterpret_cast<unsigned*>(smc + S_PL + o1) =
                pack2f(p10 - __bfloat162float(h10), p11 - __bfloat162float(h11));
        }
        __syncthreads();   // (C) P + V visible

        if (kt + 1 < nkt) {
            const int kn = k0 + 64;
#pragma unroll
            for (int t = 0; t < 4; t++) {
                int row = lrow + t * 16;
                size_t g = (size_t)(b * SEQT + kn + row) * HDIM + lq * 8;
                cp16(sb + S_KH + SWB(row, lq), g_Khi + g);
            }
            CP_COMMIT();
        }

#pragma unroll
        for (int ks2 = 0; ks2 < 4; ks2++) {
            unsigned ph[4], pl2[4];
            unsigned p_off = SWP(mi + (l & 15), ks2 * 2 + (l >> 4));
            ldsm4(ph,  sb + S_PH + p_off);
            ldsm4(pl2, sb + S_PL + p_off);
#pragma unroll
            for (int dt2 = 0; dt2 < 4; dt2++) {
                unsigned vh[4], vl[4];
                int vrow = ks2 * 16 + (l & 15);
                unsigned v_off = SWB(vrow, 8 * wj + dt2 * 2 + (l >> 4));
                ldsm4t(vh, sb + S_VH + v_off);
                ldsm4t(vl, sb + S_VL + v_off);
                mma16816(O[2 * dt2],     ph,  vh);
                mma16816(O[2 * dt2 + 1], ph,  vh + 2);
                mma16816(O[2 * dt2],     ph,  vl);
                mma16816(O[2 * dt2 + 1], ph,  vl + 2);
                mma16816(O[2 * dt2],     pl2, vh);
                mma16816(O[2 * dt2 + 1], pl2, vh + 2);
            }
        }
        __syncthreads();   // (D) PV reads done

        if (kt + 1 < nkt) {
            const int kn = k0 + 64;
#pragma unroll
            for (int t = 0; t < 4; t++) {
                int row = lrow + t * 16;
                size_t g = (size_t)(b * SEQT + kn + row) * HDIM + lq * 8;
                cp16(sb + S_VH + SWB(row, lq), g_Vhi + g);
                cp16(sb + S_VL + SWB(row, lq), g_Vlo + g);
            }
            CP_COMMIT();
        }
    }

    float inv0 = 1.0f / l0_, inv1 = 1.0f / l1_;
#pragma unroll
    for (int dt = 0; dt < 8; dt++) {
        int c = 64 * wj + dt * 8 + (l & 3) * 2;
        float2 v0 = make_float2(O[dt][0] * inv0, O[dt][1] * inv0);
        float2 v1 = make_float2(O[dt][2] * inv1, O[dt][3] * inv1);
        *reinterpret_cast<float2*>(out + ((size_t)b * SEQT + r0g) * HDIM + c) = v0;
        *reinterpret_cast<float2*>(out + ((size_t)b * SEQT + r1g) * HDIM + c) = v1;
    }
}

// ---------------------------------------------------------------------------
extern "C" void kernel_launch(void* const* d_in, const int* in_sizes, int n_in,
                              void* d_out, int out_size) {
    const float* x  = (const float*)d_in[0];
    const float* Wq = (const float*)d_in[1];
    const float* bq = (const float*)d_in[2];
    const float* Wk = (const float*)d_in[3];
    const float* bk = (const float*)d_in[4];
    const float* Wv = (const float*)d_in[5];
    const float* bv = (const float*)d_in[6];
    float* out = (float*)d_out;

    split_w_kernel<<<(3 * CDIM * HDIM) / 256, 256>>>(Wq, Wk, Wv);

    cudaFuncSetAttribute(fused_proj_kernel,
                         cudaFuncAttributeMaxDynamicSharedMemorySize, F_SMEM);
    fused_proj_kernel<<<dim3(BT / FM), 256, F_SMEM>>>(x, bq, bk, bv);

    cudaFuncSetAttribute(attn_kernel,
                         cudaFuncAttributeMaxDynamicSharedMemorySize, A_SMEM);
    attn_kernel<<<dim3(32 * BATCH), 256, A_SMEM>>>(out);
}